// round 1
// baseline (speedup 1.0000x reference)
#include <cuda_runtime.h>

// Problem constants
#define NV    32
#define DM    256
#define MM    128
#define DN    64
#define NL    3
#define BATCH 512
#define RPB   8                    // batch rows per block
#define NBLK  (BATCH / RPB)        // 64 blocks

// Scratch state (device globals: no allocations allowed)
__device__ float g_values[BATCH * NV * DM];   // 16 MB
__device__ float g_noise [BATCH * NV * DM];   // 16 MB  (gelu(nz @ ne_W + ne_b), precomputed)

typedef unsigned long long ull;

// ---- packed f32x2 helpers (FFMA2: 2x fp32 FMA throughput on sm_103a) ----
__device__ __forceinline__ ull pack2(float w) {
    ull r; asm("mov.b64 %0, {%1, %1};" : "=l"(r) : "f"(w)); return r;
}
__device__ __forceinline__ ull pack2f(float a, float b) {
    ull r; asm("mov.b64 %0, {%1, %2};" : "=l"(r) : "f"(a), "f"(b)); return r;
}
__device__ __forceinline__ void ffma2(ull &acc, ull x, ull w) {
    asm("fma.rn.f32x2 %0, %1, %2, %3;" : "=l"(acc) : "l"(x), "l"(w), "l"(acc));
}
__device__ __forceinline__ float2 asf2(ull a) {
    float2 f; asm("mov.b64 {%0, %1}, %2;" : "=f"(f.x), "=f"(f.y) : "l"(a)); return f;
}
__device__ __forceinline__ float gelu(float x) {
    return 0.5f * x * (1.0f + erff(x * 0.7071067811865476f));   // exact erf GELU
}

// ============================================================================
// Kernel 1: noise encoder precompute.
// g_noise[b][i][d] = gelu( sum_k nz[b][i][k] * ne_W[i][k][d] + ne_b[i][d] )
// grid (16 batch-chunks, 32 vars), 256 threads = d
// ============================================================================
__global__ void __launch_bounds__(256, 4) noise_kernel(
    const float* __restrict__ nz,    // (B, NV, DN)
    const float* __restrict__ neW,   // (NV, DN, DM)
    const float* __restrict__ neb)   // (NV, DM)
{
    const int i = blockIdx.y;
    const int chunk = blockIdx.x;
    const int d = threadIdx.x;

    __shared__ float s_nz[32][DN];
    for (int idx = d; idx < 32 * DN; idx += 256) {
        int r = idx / DN, k = idx % DN;
        int b = chunk * 32 + r;
        s_nz[r][k] = nz[(b * NV + i) * DN + k];
    }
    __syncthreads();

    const float bias = neb[i * DM + d];
    const float* __restrict__ W = neW + i * DN * DM;
    for (int r = 0; r < 32; r++) {
        float acc = bias;
        #pragma unroll 16
        for (int k = 0; k < DN; k++)
            acc += s_nz[r][k] * __ldg(W + k * DM + d);
        int b = chunk * 32 + r;
        g_noise[(b * NV + i) * DM + d] = gelu(acc);
    }
}

// ============================================================================
// GEMM micro-phases. Activations live in smem as buf[dim][RPB] (row-pairs are
// contiguous so FFMA2 can consume them as 64-bit lanes). Weights are [K][N]
// row-major -> thread j streams column j with fully coalesced LDGs.
// ============================================================================

// N_out = 256: thread t -> output col j=t, accumulates all 8 rows (4 pairs).
template<int K, bool DOGELU>
__device__ __forceinline__ void gemm_n256(
    const float* __restrict__ sin, float* __restrict__ sout,
    const float* __restrict__ W, float bias, int j)
{
    ull b2 = pack2(bias);
    ull acc0 = b2, acc1 = b2, acc2 = b2, acc3 = b2;
    const float* __restrict__ w = W + j;
    #pragma unroll 4
    for (int d = 0; d < K; d++) {
        ull w2 = pack2(__ldg(w)); w += 256;
        const ulonglong2* p = reinterpret_cast<const ulonglong2*>(sin + d * RPB);
        ulonglong2 xa = p[0];   // rows 0..3 (two f32x2 lanes)
        ulonglong2 xb = p[1];   // rows 4..7
        ffma2(acc0, xa.x, w2); ffma2(acc1, xa.y, w2);
        ffma2(acc2, xb.x, w2); ffma2(acc3, xb.y, w2);
    }
    float2 f0 = asf2(acc0), f1 = asf2(acc1), f2 = asf2(acc2), f3 = asf2(acc3);
    if (DOGELU) {
        f0.x = gelu(f0.x); f0.y = gelu(f0.y); f1.x = gelu(f1.x); f1.y = gelu(f1.y);
        f2.x = gelu(f2.x); f2.y = gelu(f2.y); f3.x = gelu(f3.x); f3.y = gelu(f3.y);
    }
    reinterpret_cast<float4*>(sout + j * RPB)[0] = make_float4(f0.x, f0.y, f1.x, f1.y);
    reinterpret_cast<float4*>(sout + j * RPB)[1] = make_float4(f2.x, f2.y, f3.x, f3.y);
}

// N_out = 128: j = t & 127, half = t >> 7 handles rows half*4..half*4+3.
template<int K>
__device__ __forceinline__ void gemm_n128(
    const float* __restrict__ sin, float* __restrict__ sout,
    const float* __restrict__ W, float bias, int t)
{
    const int j  = t & 127;
    const int rb = (t >> 7) * 4;
    ull b2 = pack2(bias);
    ull acc0 = b2, acc1 = b2;
    const float* __restrict__ w = W + j;
    #pragma unroll 4
    for (int d = 0; d < K; d++) {
        ull w2 = pack2(__ldg(w)); w += 128;
        ulonglong2 xa = reinterpret_cast<const ulonglong2*>(sin + d * RPB + rb)[0];
        ffma2(acc0, xa.x, w2); ffma2(acc1, xa.y, w2);
    }
    float2 f0 = asf2(acc0), f1 = asf2(acc1);
    f0.x = gelu(f0.x); f0.y = gelu(f0.y); f1.x = gelu(f1.x); f1.y = gelu(f1.y);
    reinterpret_cast<float4*>(sout + j * RPB + rb)[0] = make_float4(f0.x, f0.y, f1.x, f1.y);
}

// ============================================================================
// Main kernel: each block owns RPB=8 batch rows and runs the full
// 3-layer x 32-variable sequential scan privately. No inter-block deps.
// ============================================================================
__global__ void __launch_bounds__(256, 1) scm_kernel(
    const float* __restrict__ edge_logits,  // (NV, NV)
    const float* __restrict__ var_emb,      // (NV, DM)
    const float* __restrict__ paW,          // (DM, DM)
    const float* __restrict__ pab,          // (DM)
    const float* __restrict__ mW1,          // (NV, DM, MM)
    const float* __restrict__ mb1,          // (NV, MM)
    const float* __restrict__ mW2,          // (NV, MM, MM)
    const float* __restrict__ mb2,          // (NV, MM)
    const float* __restrict__ mW3,          // (NV, MM, DM)
    const float* __restrict__ mb3,          // (NV, DM)
    float* __restrict__ out)                // (B, NV, DM)
{
    __shared__ float s_adj[NV * NV];                 // s_adj[i*32+v] = adj(v -> i)
    __shared__ __align__(16) float s_a[DM * RPB];    // ping
    __shared__ __align__(16) float s_b[DM * RPB];    // pong

    const int t = threadIdx.x;
    const int row0 = blockIdx.x * RPB;

    // adjacency: sigmoid((logits * offdiag_mask) / 0.5). Diagonal -> sigmoid(0)=0.5.
    for (int idx = t; idx < NV * NV; idx += 256) {
        int ii = idx / NV, v = idx % NV;
        float z = (v == ii) ? 0.0f : edge_logits[v * NV + ii] * 2.0f;
        s_adj[idx] = 1.0f / (1.0f + expf(-z));
    }
    // zero this block's value rows
    float4 z4 = make_float4(0.f, 0.f, 0.f, 0.f);
    float4* vz = reinterpret_cast<float4*>(g_values + row0 * NV * DM);
    for (int idx = t; idx < RPB * NV * DM / 4; idx += 256) vz[idx] = z4;
    __syncthreads();

    for (int layer = 0; layer < NL; layer++) {
        for (int i = 0; i < NV; i++) {
            // ---- phase pc: s_a[d][r] = emb[i][d] + sum_v adj[v->i] * values[r][v][d]
            {
                const int d0 = (t & 127) * 2;     // even dim pair
                const int rb = (t >> 7) * 4;      // 4 rows per thread
                const float2 e = *reinterpret_cast<const float2*>(var_emb + i * DM + d0);
                ull e2 = pack2f(e.x, e.y);
                ull acc0 = e2, acc1 = e2, acc2 = e2, acc3 = e2;
                const ull* __restrict__ base =
                    reinterpret_cast<const ull*>(g_values + (row0 + rb) * (NV * DM) + d0);
                const int rstride = (NV * DM) / 2;   // in ull units
                #pragma unroll 4
                for (int v = 0; v < NV; v++) {
                    ull a2 = pack2(s_adj[i * NV + v]);
                    const ull* p = base + v * (DM / 2);
                    ffma2(acc0, __ldg(p),               a2);
                    ffma2(acc1, __ldg(p + rstride),     a2);
                    ffma2(acc2, __ldg(p + 2 * rstride), a2);
                    ffma2(acc3, __ldg(p + 3 * rstride), a2);
                }
                float2 f0 = asf2(acc0), f1 = asf2(acc1), f2 = asf2(acc2), f3 = asf2(acc3);
                *reinterpret_cast<float4*>(s_a + d0 * RPB + rb) =
                    make_float4(f0.x, f1.x, f2.x, f3.x);
                *reinterpret_cast<float4*>(s_a + (d0 + 1) * RPB + rb) =
                    make_float4(f0.y, f1.y, f2.y, f3.y);
            }
            __syncthreads();

            // ---- parent_input = gelu(x @ paW + pab) : 256 -> 256
            gemm_n256<DM, true>(s_a, s_b, paW, pab[t], t);
            __syncthreads();

            // ---- h1 = gelu(parent @ W1 + b1) : 256 -> 128
            gemm_n128<DM>(s_b, s_a, mW1 + i * DM * MM, mb1[i * MM + (t & 127)], t);
            __syncthreads();

            // ---- h2 = gelu(h1 @ W2 + b2) : 128 -> 128
            gemm_n128<MM>(s_a, s_b, mW2 + i * MM * MM, mb2[i * MM + (t & 127)], t);
            __syncthreads();

            // ---- out = h2 @ W3 + b3 + noise ; write values (and final output)
            {
                const int j = t;
                ull b2 = pack2(mb3[i * DM + j]);
                ull acc0 = b2, acc1 = b2, acc2 = b2, acc3 = b2;
                const float* __restrict__ w = mW3 + i * MM * DM + j;
                #pragma unroll 4
                for (int d = 0; d < MM; d++) {
                    ull w2 = pack2(__ldg(w)); w += 256;
                    const ulonglong2* p = reinterpret_cast<const ulonglong2*>(s_b + d * RPB);
                    ulonglong2 xa = p[0], xb = p[1];
                    ffma2(acc0, xa.x, w2); ffma2(acc1, xa.y, w2);
                    ffma2(acc2, xb.x, w2); ffma2(acc3, xb.y, w2);
                }
                float2 f[4] = { asf2(acc0), asf2(acc1), asf2(acc2), asf2(acc3) };
                #pragma unroll
                for (int q = 0; q < 4; q++) {
                    int r0 = 2 * q;
                    long long base0 = (long long)(row0 + r0) * (NV * DM) + i * DM + j;
                    long long base1 = base0 + (NV * DM);
                    float v0 = f[q].x + __ldg(g_noise + base0);
                    float v1 = f[q].y + __ldg(g_noise + base1);
                    g_values[base0] = v0;
                    g_values[base1] = v1;
                    if (layer == NL - 1) { out[base0] = v0; out[base1] = v1; }
                }
            }
            __syncthreads();
        }
    }
}

// ============================================================================
// Launch
// ============================================================================
extern "C" void kernel_launch(void* const* d_in, const int* in_sizes, int n_in,
                              void* d_out, int out_size)
{
    const float* nz   = (const float*)d_in[0];   // exogenous_noise (512,32,64)
    const float* elog = (const float*)d_in[1];   // edge_logits (32,32)
    const float* emb  = (const float*)d_in[2];   // var_emb (32,256)
    const float* paW  = (const float*)d_in[3];   // (256,256)
    const float* pab  = (const float*)d_in[4];   // (256)
    const float* mW1  = (const float*)d_in[5];   // (32,256,128)
    const float* mb1  = (const float*)d_in[6];   // (32,128)
    const float* mW2  = (const float*)d_in[7];   // (32,128,128)
    const float* mb2  = (const float*)d_in[8];   // (32,128)
    const float* mW3  = (const float*)d_in[9];   // (32,128,256)
    const float* mb3  = (const float*)d_in[10];  // (32,256)
    const float* neW  = (const float*)d_in[11];  // (32,64,256)
    const float* neb  = (const float*)d_in[12];  // (32,256)
    float* out = (float*)d_out;                  // (512,32,256)

    noise_kernel<<<dim3(BATCH / 32, NV), 256>>>(nz, neW, neb);
    scm_kernel<<<NBLK, 256>>>(elog, emb, paW, pab, mW1, mb1, mW2, mb2, mW3, mb3, out);
}

// round 2
// speedup vs baseline: 1.6038x; 1.6038x over previous
#include <cuda_runtime.h>

// Problem constants
#define NV    32
#define DM    256
#define MM    128
#define DN    64
#define NL    3
#define BATCH 512
#define RPB   8                    // batch rows per block
#define NBLK  (BATCH / RPB)        // 64 blocks
#define SP    9                    // padded row stride (in ull) for splat buffers

// Scratch state (device globals: no allocations allowed)
__device__ float g_values[BATCH * NV * DM];   // 16 MB
__device__ float g_noise [BATCH * NV * DM];   // 16 MB (gelu(nz @ ne_W + ne_b))

typedef unsigned long long ull;

// ---- packed f32x2 helpers (FFMA2: 2x fp32 FMA throughput on sm_103a) ----
__device__ __forceinline__ ull pack2(float w) {
    ull r; asm("mov.b64 %0, {%1, %1};" : "=l"(r) : "f"(w)); return r;
}
__device__ __forceinline__ ull pack2f(float a, float b) {
    ull r; asm("mov.b64 %0, {%1, %2};" : "=l"(r) : "f"(a), "f"(b)); return r;
}
__device__ __forceinline__ void ffma2(ull &acc, ull x, ull w) {
    asm("fma.rn.f32x2 %0, %1, %2, %3;" : "=l"(acc) : "l"(x), "l"(w), "l"(acc));
}
__device__ __forceinline__ float2 asf2(ull a) {
    float2 f; asm("mov.b64 {%0, %1}, %2;" : "=f"(f.x), "=f"(f.y) : "l"(a)); return f;
}
__device__ __forceinline__ float gelu(float x) {
    return 0.5f * x * (1.0f + erff(x * 0.7071067811865476f));   // exact erf GELU
}

// ============================================================================
// Kernel 1: noise encoder precompute.
// ============================================================================
__global__ void __launch_bounds__(256, 4) noise_kernel(
    const float* __restrict__ nz,    // (B, NV, DN)
    const float* __restrict__ neW,   // (NV, DN, DM)
    const float* __restrict__ neb)   // (NV, DM)
{
    const int i = blockIdx.y;
    const int chunk = blockIdx.x;
    const int d = threadIdx.x;

    __shared__ float s_nz[32][DN];
    for (int idx = d; idx < 32 * DN; idx += 256) {
        int r = idx / DN, k = idx % DN;
        int b = chunk * 32 + r;
        s_nz[r][k] = nz[(b * NV + i) * DN + k];
    }
    __syncthreads();

    const float bias = neb[i * DM + d];
    const float* __restrict__ W = neW + i * DN * DM;
    for (int r = 0; r < 32; r++) {
        float acc = bias;
        #pragma unroll 16
        for (int k = 0; k < DN; k++)
            acc += s_nz[r][k] * __ldg(W + k * DM + d);
        int b = chunk * 32 + r;
        g_noise[(b * NV + i) * DM + d] = gelu(acc);
    }
}

// ============================================================================
// GEMM micro-phases.
// Activations: smem splat layout  s[d*SP + r] = (x, x) as a 64-bit word.
// Weights: row-major [K][N], loaded as LDG.128 -> ulonglong2 = two f32x2
// column-pair lanes. Thread owns 4 consecutive output columns.
// ============================================================================

// N_out = 256: thread t -> cols jg..jg+3, rows rp, rp+1  (256 thr = 64x4)
template<int K, bool DOGELU>
__device__ __forceinline__ void phase_n256(
    const ull* __restrict__ sin, ull* __restrict__ sout,
    const float* __restrict__ W, const float* __restrict__ bias, int t)
{
    const int jg = (t & 63) * 4;
    const int rp = (t >> 6) * 2;
    const float4 b4 = __ldg(reinterpret_cast<const float4*>(bias + jg));
    const ull bA = pack2f(b4.x, b4.y), bB = pack2f(b4.z, b4.w);
    ull a00 = bA, a01 = bB, a10 = bA, a11 = bB;
    const ulonglong2* __restrict__ wp =
        reinterpret_cast<const ulonglong2*>(W + jg);     // row stride: 256 fl = 64 u2
    #pragma unroll 16
    for (int d = 0; d < K; d++) {
        ulonglong2 w = __ldg(wp + (size_t)d * 64);
        ull x0 = sin[d * SP + rp];
        ull x1 = sin[d * SP + rp + 1];
        ffma2(a00, x0, w.x); ffma2(a01, x0, w.y);
        ffma2(a10, x1, w.x); ffma2(a11, x1, w.y);
    }
    float2 f00 = asf2(a00), f01 = asf2(a01), f10 = asf2(a10), f11 = asf2(a11);
    if (DOGELU) {
        f00.x = gelu(f00.x); f00.y = gelu(f00.y);
        f01.x = gelu(f01.x); f01.y = gelu(f01.y);
        f10.x = gelu(f10.x); f10.y = gelu(f10.y);
        f11.x = gelu(f11.x); f11.y = gelu(f11.y);
    }
    sout[(jg + 0) * SP + rp]     = pack2(f00.x);
    sout[(jg + 1) * SP + rp]     = pack2(f00.y);
    sout[(jg + 2) * SP + rp]     = pack2(f01.x);
    sout[(jg + 3) * SP + rp]     = pack2(f01.y);
    sout[(jg + 0) * SP + rp + 1] = pack2(f10.x);
    sout[(jg + 1) * SP + rp + 1] = pack2(f10.y);
    sout[(jg + 2) * SP + rp + 1] = pack2(f11.x);
    sout[(jg + 3) * SP + rp + 1] = pack2(f11.y);
}

// N_out = 128: thread t -> cols jg..jg+3 (jg = (t&31)*4), row r = t>>5
template<int K>
__device__ __forceinline__ void phase_n128(
    const ull* __restrict__ sin, ull* __restrict__ sout,
    const float* __restrict__ W, const float* __restrict__ bias, int t)
{
    const int jg = (t & 31) * 4;
    const int r  = t >> 5;
    const float4 b4 = __ldg(reinterpret_cast<const float4*>(bias + jg));
    ull a0 = pack2f(b4.x, b4.y), a1 = pack2f(b4.z, b4.w);
    const ulonglong2* __restrict__ wp =
        reinterpret_cast<const ulonglong2*>(W + jg);     // row stride: 128 fl = 32 u2
    #pragma unroll 16
    for (int d = 0; d < K; d++) {
        ulonglong2 w = __ldg(wp + (size_t)d * 32);
        ull x = sin[d * SP + r];
        ffma2(a0, x, w.x); ffma2(a1, x, w.y);
    }
    float2 f0 = asf2(a0), f1 = asf2(a1);
    sout[(jg + 0) * SP + r] = pack2(gelu(f0.x));
    sout[(jg + 1) * SP + r] = pack2(gelu(f0.y));
    sout[(jg + 2) * SP + r] = pack2(gelu(f1.x));
    sout[(jg + 3) * SP + r] = pack2(gelu(f1.y));
}

// ============================================================================
// Main kernel
// ============================================================================
__global__ void __launch_bounds__(256, 1) scm_kernel(
    const float* __restrict__ edge_logits,  // (NV, NV)
    const float* __restrict__ var_emb,      // (NV, DM)
    const float* __restrict__ paW,          // (DM, DM)
    const float* __restrict__ pab,          // (DM)
    const float* __restrict__ mW1,          // (NV, DM, MM)
    const float* __restrict__ mb1,          // (NV, MM)
    const float* __restrict__ mW2,          // (NV, MM, MM)
    const float* __restrict__ mb2,          // (NV, MM)
    const float* __restrict__ mW3,          // (NV, MM, DM)
    const float* __restrict__ mb3,          // (NV, DM)
    float* __restrict__ out)                // (B, NV, DM)
{
    __shared__ float s_adj[NV * NV];                    // s_adj[i*32+v] = adj(v -> i)
    __shared__ __align__(16) ull s_a[DM * SP];          // ping (splat layout)
    __shared__ __align__(16) ull s_b[DM * SP];          // pong

    const int t = threadIdx.x;
    const int row0 = blockIdx.x * RPB;

    // adjacency: sigmoid((logits * offdiag_mask) / 0.5). Diagonal -> 0.5.
    for (int idx = t; idx < NV * NV; idx += 256) {
        int ii = idx / NV, v = idx % NV;
        float z = (v == ii) ? 0.0f : edge_logits[v * NV + ii] * 2.0f;
        s_adj[idx] = 1.0f / (1.0f + expf(-z));
    }
    // zero this block's value rows
    float4 z4 = make_float4(0.f, 0.f, 0.f, 0.f);
    float4* vz = reinterpret_cast<float4*>(g_values + row0 * NV * DM);
    for (int idx = t; idx < RPB * NV * DM / 4; idx += 256) vz[idx] = z4;
    __syncthreads();

    for (int layer = 0; layer < NL; layer++) {
        for (int i = 0; i < NV; i++) {
            // ---- pc: s_a[d][r] = splat( emb[i][d] + sum_v adj[v->i]*values[r][v][d] )
            {
                const int d0 = (t & 127) * 2;     // even dim pair
                const int rb = (t >> 7) * 4;      // 4 rows per thread
                const float2 e = *reinterpret_cast<const float2*>(var_emb + i * DM + d0);
                ull e2 = pack2f(e.x, e.y);
                ull acc0 = e2, acc1 = e2, acc2 = e2, acc3 = e2;
                const ull* __restrict__ base =
                    reinterpret_cast<const ull*>(g_values + (row0 + rb) * (NV * DM) + d0);
                const int rstride = (NV * DM) / 2;   // in ull units
                #pragma unroll 4
                for (int v = 0; v < NV; v++) {
                    ull a2 = pack2(s_adj[i * NV + v]);
                    const ull* p = base + v * (DM / 2);
                    ffma2(acc0, __ldg(p),               a2);
                    ffma2(acc1, __ldg(p + rstride),     a2);
                    ffma2(acc2, __ldg(p + 2 * rstride), a2);
                    ffma2(acc3, __ldg(p + 3 * rstride), a2);
                }
                float2 f0 = asf2(acc0), f1 = asf2(acc1), f2 = asf2(acc2), f3 = asf2(acc3);
                s_a[d0 * SP + rb + 0]       = pack2(f0.x);
                s_a[d0 * SP + rb + 1]       = pack2(f1.x);
                s_a[d0 * SP + rb + 2]       = pack2(f2.x);
                s_a[d0 * SP + rb + 3]       = pack2(f3.x);
                s_a[(d0 + 1) * SP + rb + 0] = pack2(f0.y);
                s_a[(d0 + 1) * SP + rb + 1] = pack2(f1.y);
                s_a[(d0 + 1) * SP + rb + 2] = pack2(f2.y);
                s_a[(d0 + 1) * SP + rb + 3] = pack2(f3.y);
            }
            __syncthreads();

            // ---- parent_input = gelu(x @ paW + pab) : 256 -> 256
            phase_n256<DM, true>(s_a, s_b, paW, pab, t);
            __syncthreads();

            // ---- h1 = gelu(parent @ W1 + b1) : 256 -> 128
            phase_n128<DM>(s_b, s_a, mW1 + i * DM * MM, mb1 + i * MM, t);
            __syncthreads();

            // ---- h2 = gelu(h1 @ W2 + b2) : 128 -> 128
            phase_n128<MM>(s_a, s_b, mW2 + i * MM * MM, mb2 + i * MM, t);
            __syncthreads();

            // ---- out = h2 @ W3 + b3 + noise ; write values (and final output)
            {
                const int jg = (t & 63) * 4;
                const int rp = (t >> 6) * 2;
                const float4 b4 = __ldg(reinterpret_cast<const float4*>(mb3 + i * DM + jg));
                const ull bA = pack2f(b4.x, b4.y), bB = pack2f(b4.z, b4.w);
                ull a00 = bA, a01 = bB, a10 = bA, a11 = bB;
                const ulonglong2* __restrict__ wp =
                    reinterpret_cast<const ulonglong2*>(mW3 + i * MM * DM + jg);
                #pragma unroll 16
                for (int d = 0; d < MM; d++) {
                    ulonglong2 w = __ldg(wp + (size_t)d * 64);
                    ull x0 = s_b[d * SP + rp];
                    ull x1 = s_b[d * SP + rp + 1];
                    ffma2(a00, x0, w.x); ffma2(a01, x0, w.y);
                    ffma2(a10, x1, w.x); ffma2(a11, x1, w.y);
                }
                float2 f00 = asf2(a00), f01 = asf2(a01);
                float2 f10 = asf2(a10), f11 = asf2(a11);

                long long base0 = ((long long)(row0 + rp) * NV + i) * DM + jg;
                long long base1 = base0 + (long long)NV * DM;
                float4 n0 = __ldg(reinterpret_cast<const float4*>(g_noise + base0));
                float4 n1 = __ldg(reinterpret_cast<const float4*>(g_noise + base1));
                float4 v0 = make_float4(f00.x + n0.x, f00.y + n0.y,
                                        f01.x + n0.z, f01.y + n0.w);
                float4 v1 = make_float4(f10.x + n1.x, f10.y + n1.y,
                                        f11.x + n1.z, f11.y + n1.w);
                *reinterpret_cast<float4*>(g_values + base0) = v0;
                *reinterpret_cast<float4*>(g_values + base1) = v1;
                if (layer == NL - 1) {
                    *reinterpret_cast<float4*>(out + base0) = v0;
                    *reinterpret_cast<float4*>(out + base1) = v1;
                }
            }
            __syncthreads();
        }
    }
}

// ============================================================================
// Launch
// ============================================================================
extern "C" void kernel_launch(void* const* d_in, const int* in_sizes, int n_in,
                              void* d_out, int out_size)
{
    const float* nz   = (const float*)d_in[0];   // exogenous_noise (512,32,64)
    const float* elog = (const float*)d_in[1];   // edge_logits (32,32)
    const float* emb  = (const float*)d_in[2];   // var_emb (32,256)
    const float* paW  = (const float*)d_in[3];   // (256,256)
    const float* pab  = (const float*)d_in[4];   // (256)
    const float* mW1  = (const float*)d_in[5];   // (32,256,128)
    const float* mb1  = (const float*)d_in[6];   // (32,128)
    const float* mW2  = (const float*)d_in[7];   // (32,128,128)
    const float* mb2  = (const float*)d_in[8];   // (32,128)
    const float* mW3  = (const float*)d_in[9];   // (32,128,256)
    const float* mb3  = (const float*)d_in[10];  // (32,256)
    const float* neW  = (const float*)d_in[11];  // (32,64,256)
    const float* neb  = (const float*)d_in[12];  // (32,256)
    float* out = (float*)d_out;                  // (512,32,256)

    noise_kernel<<<dim3(BATCH / 32, NV), 256>>>(nz, neW, neb);
    scm_kernel<<<NBLK, 256>>>(elog, emb, paW, pab, mW1, mb1, mW2, mb2, mW3, mb3, out);
}

// round 3
// speedup vs baseline: 2.0659x; 1.2881x over previous
#include <cuda_runtime.h>

// Problem constants
#define NV    32
#define DM    256
#define MM    128
#define DN    64
#define NL    3
#define BATCH 512
#define RPB   8                    // batch rows per block
#define NBLK  (BATCH / RPB)        // 64 blocks
#define SP    10                   // padded row stride (ull) in splat buffers (even for LDS.128)
#define NVDM  (NV * DM)

// Scratch state (device globals: no allocations allowed)
__device__ float g_values[BATCH * NV * DM];   // 16 MB
__device__ float g_noise [BATCH * NV * DM];   // 16 MB (gelu(nz @ ne_W + ne_b))

typedef unsigned long long ull;

// ---- packed f32x2 helpers ----
__device__ __forceinline__ ull pack2(float w) {
    ull r; asm("mov.b64 %0, {%1, %1};" : "=l"(r) : "f"(w)); return r;
}
__device__ __forceinline__ ull pack2f(float a, float b) {
    ull r; asm("mov.b64 %0, {%1, %2};" : "=l"(r) : "f"(a), "f"(b)); return r;
}
__device__ __forceinline__ void ffma2(ull &acc, ull x, ull w) {
    asm("fma.rn.f32x2 %0, %1, %2, %3;" : "=l"(acc) : "l"(x), "l"(w), "l"(acc));
}
__device__ __forceinline__ ull fadd2(ull a, ull b) {
    ull r; asm("add.rn.f32x2 %0, %1, %2;" : "=l"(r) : "l"(a), "l"(b)); return r;
}
__device__ __forceinline__ float2 asf2(ull a) {
    float2 f; asm("mov.b64 {%0, %1}, %2;" : "=f"(f.x), "=f"(f.y) : "l"(a)); return f;
}
__device__ __forceinline__ float gelu(float x) {
    return 0.5f * x * (1.0f + erff(x * 0.7071067811865476f));   // exact erf GELU
}

// ============================================================================
// Kernel 1: noise encoder precompute (weights loaded once, FFMA2 over rowpairs)
// ============================================================================
__global__ void __launch_bounds__(256, 2) noise_kernel(
    const float* __restrict__ nz,    // (B, NV, DN)
    const float* __restrict__ neW,   // (NV, DN, DM)
    const float* __restrict__ neb)   // (NV, DM)
{
    const int i = blockIdx.y;
    const int chunk = blockIdx.x;
    const int d = threadIdx.x;

    __shared__ __align__(16) ull s_nzp[DN][16];  // [k][rowpair] splat-pairs, 8KB
    for (int idx = d; idx < DN * 16; idx += 256) {
        int k = idx >> 4, rp = idx & 15;
        int b = chunk * 32 + rp * 2;
        s_nzp[k][rp] = pack2f(nz[(b * NV + i) * DN + k],
                              nz[((b + 1) * NV + i) * DN + k]);
    }
    __syncthreads();

    ull acc[16];
    #pragma unroll
    for (int rp = 0; rp < 16; rp++) acc[rp] = 0;

    const float* __restrict__ W = neW + i * DN * DM + d;
    #pragma unroll 2
    for (int k = 0; k < DN; k++) {
        ull w2 = pack2(__ldg(W + k * DM));
        const ulonglong2* row = reinterpret_cast<const ulonglong2*>(s_nzp[k]);
        #pragma unroll
        for (int j = 0; j < 8; j++) {
            ulonglong2 x = row[j];
            ffma2(acc[2 * j],     x.x, w2);
            ffma2(acc[2 * j + 1], x.y, w2);
        }
    }
    const float bias = neb[i * DM + d];
    #pragma unroll
    for (int rp = 0; rp < 16; rp++) {
        float2 f = asf2(acc[rp]);
        int b = chunk * 32 + rp * 2;
        g_noise[((long long)b * NV + i) * DM + d]       = gelu(f.x + bias);
        g_noise[((long long)(b + 1) * NV + i) * DM + d] = gelu(f.y + bias);
    }
}

// ============================================================================
// Split-K partial GEMM. Thread owns 8 cols x 4 rows x K-chunk. dup = 1:
// every weight element loaded exactly once per block.
// Activations read as LDS.128 of splats (warp-broadcast).
// ============================================================================
template<int N, int K>
__device__ __forceinline__ void split_partial(
    const ull* __restrict__ sin, ull* __restrict__ red,
    const float* __restrict__ W, int t)
{
    constexpr int CG  = N / 8;                 // column groups (8 cols each)
    constexpr int LCG = (N == 256) ? 5 : 4;
    constexpr int KS  = 256 >> (LCG + 1);      // K splits: 4 (N=256) / 8 (N=128)
    constexpr int CHUNK = K / KS;
    const int cg = t & (CG - 1);
    const int rs = (t >> LCG) & 1;
    const int ks = t >> (LCG + 1);
    const int jg = cg * 8;
    const int r0 = rs * 4;

    ull a[4][4];                               // [colpair][row]
    #pragma unroll
    for (int c = 0; c < 4; c++)
        #pragma unroll
        for (int ri = 0; ri < 4; ri++) a[c][ri] = 0;

    const ulonglong2* __restrict__ wp =
        reinterpret_cast<const ulonglong2*>(W + (size_t)(ks * CHUNK) * N) + (jg >> 2);
    const ull* __restrict__ xin = sin + (ks * CHUNK) * SP + r0;

    #pragma unroll 4
    for (int d = 0; d < CHUNK; d++) {
        ulonglong2 w0 = __ldg(wp + d * (N / 4));        // cols jg..jg+3
        ulonglong2 w1 = __ldg(wp + d * (N / 4) + 1);    // cols jg+4..jg+7
        ulonglong2 x01 = *reinterpret_cast<const ulonglong2*>(xin + d * SP);
        ulonglong2 x23 = *reinterpret_cast<const ulonglong2*>(xin + d * SP + 2);
        ffma2(a[0][0], x01.x, w0.x); ffma2(a[0][1], x01.y, w0.x);
        ffma2(a[0][2], x23.x, w0.x); ffma2(a[0][3], x23.y, w0.x);
        ffma2(a[1][0], x01.x, w0.y); ffma2(a[1][1], x01.y, w0.y);
        ffma2(a[1][2], x23.x, w0.y); ffma2(a[1][3], x23.y, w0.y);
        ffma2(a[2][0], x01.x, w1.x); ffma2(a[2][1], x01.y, w1.x);
        ffma2(a[2][2], x23.x, w1.x); ffma2(a[2][3], x23.y, w1.x);
        ffma2(a[3][0], x01.x, w1.y); ffma2(a[3][1], x01.y, w1.y);
        ffma2(a[3][2], x23.x, w1.y); ffma2(a[3][3], x23.y, w1.y);
    }
    // partial layout: red[((cp*8 + r)*KS + ks)*CG + cg]  (lanes stride-1 -> no conflicts)
    #pragma unroll
    for (int c = 0; c < 4; c++)
        #pragma unroll
        for (int ri = 0; ri < 4; ri++)
            red[(((c * 8) + r0 + ri) * KS + ks) * CG + cg] = a[c][ri];
}

// ---- reducers: sum KS partials, +bias, gelu, write splat buffer ----
__device__ __forceinline__ void reduce_256(
    const ull* __restrict__ red, ull* __restrict__ sout,
    const float* __restrict__ bias, int t)
{
    const int cp  = t & 3;
    const int cg2 = (t >> 2) & 31;
    const int rg  = t >> 7;
    const int cpG = cg2 * 4 + cp;
    const int col0 = cpG * 2;
    const float2 bb = __ldg(reinterpret_cast<const float2*>(bias) + cpG);
    const ull b2 = pack2f(bb.x, bb.y);
    float glo[4], ghi[4];
    #pragma unroll
    for (int ri = 0; ri < 4; ri++) {
        const int r = rg * 4 + ri;
        const ull* p = red + ((cp * 8 + r) * 4) * 32 + cg2;
        ull s = fadd2(fadd2(p[0], p[32]), fadd2(p[64], p[96]));
        s = fadd2(s, b2);
        float2 f = asf2(s);
        glo[ri] = gelu(f.x); ghi[ri] = gelu(f.y);
    }
    ulonglong2* o0 = reinterpret_cast<ulonglong2*>(sout + col0 * SP + rg * 4);
    o0[0] = make_ulonglong2(pack2(glo[0]), pack2(glo[1]));
    o0[1] = make_ulonglong2(pack2(glo[2]), pack2(glo[3]));
    ulonglong2* o1 = reinterpret_cast<ulonglong2*>(sout + (col0 + 1) * SP + rg * 4);
    o1[0] = make_ulonglong2(pack2(ghi[0]), pack2(ghi[1]));
    o1[1] = make_ulonglong2(pack2(ghi[2]), pack2(ghi[3]));
}

__device__ __forceinline__ void reduce_128(
    const ull* __restrict__ red, ull* __restrict__ sout,
    const float* __restrict__ bias, int t)
{
    const int cp  = t & 3;
    const int cg2 = (t >> 2) & 15;
    const int rpair = t >> 6;
    const int cpG = cg2 * 4 + cp;
    const int col0 = cpG * 2;
    const float2 bb = __ldg(reinterpret_cast<const float2*>(bias) + cpG);
    const ull b2 = pack2f(bb.x, bb.y);
    float glo[2], ghi[2];
    #pragma unroll
    for (int rr = 0; rr < 2; rr++) {
        const int r = rpair * 2 + rr;
        const ull* p = red + ((cp * 8 + r) * 8) * 16 + cg2;
        ull s = fadd2(fadd2(fadd2(p[0], p[16]), fadd2(p[32], p[48])),
                      fadd2(fadd2(p[64], p[80]), fadd2(p[96], p[112])));
        s = fadd2(s, b2);
        float2 f = asf2(s);
        glo[rr] = gelu(f.x); ghi[rr] = gelu(f.y);
    }
    *reinterpret_cast<ulonglong2*>(sout + col0 * SP + rpair * 2) =
        make_ulonglong2(pack2(glo[0]), pack2(glo[1]));
    *reinterpret_cast<ulonglong2*>(sout + (col0 + 1) * SP + rpair * 2) =
        make_ulonglong2(pack2(ghi[0]), pack2(ghi[1]));
}

// ============================================================================
// Main kernel
// ============================================================================
__global__ void __launch_bounds__(256, 1) scm_kernel(
    const float* __restrict__ edge_logits,
    const float* __restrict__ var_emb,
    const float* __restrict__ paW,  const float* __restrict__ pab,
    const float* __restrict__ mW1,  const float* __restrict__ mb1,
    const float* __restrict__ mW2,  const float* __restrict__ mb2,
    const float* __restrict__ mW3,  const float* __restrict__ mb3,
    float* __restrict__ out)
{
    extern __shared__ __align__(16) ull smem[];
    ull* s_red  = smem;                 // 4096 ull = 32KB
    ull* s_a    = smem + 4096;          // 2560 ull = 20KB (splat layout [d][row])
    ull* s_b    = smem + 6656;          // 2560 ull
    ull* s_adj2 = smem + 9216;          // 1024 ull = 8KB (splat adjacency)

    const int t = threadIdx.x;
    const int row0 = blockIdx.x * RPB;

    // adjacency: sigmoid((logits * offdiag)/0.5); diagonal -> sigmoid(0)=0.5
    for (int idx = t; idx < NV * NV; idx += 256) {
        int ii = idx / NV, v = idx % NV;
        float z = (v == ii) ? 0.0f : edge_logits[v * NV + ii] * 2.0f;
        s_adj2[idx] = pack2(1.0f / (1.0f + expf(-z)));
    }
    __syncthreads();

    for (int layer = 0; layer < NL; layer++) {
        const bool last = (layer == NL - 1);
        for (int i = 0; i < NV; i++) {
            // ---- pc: s_a[d][r] = splat( emb[i][d] + sum_v adj[v->i]*values[r][v][d] )
            {
                const int d0 = (t & 127) * 2;
                const int rb = (t >> 7) * 4;
                const float2 e = __ldg(reinterpret_cast<const float2*>(var_emb + i * DM + d0));
                ull e2 = pack2f(e.x, e.y);
                ull acc0 = e2, acc1 = e2, acc2 = e2, acc3 = e2;
                const ull* __restrict__ base =
                    reinterpret_cast<const ull*>(g_values + (long long)(row0 + rb) * NVDM) + (d0 >> 1);
                const int rstride = NVDM / 2;
                const int vmax = (layer == 0) ? i : NV;   // layer 0: later vars still zero
                #pragma unroll 4
                for (int v = 0; v < vmax; v++) {
                    ull a2 = s_adj2[i * NV + v];
                    const ull* p = base + v * (DM / 2);
                    ffma2(acc0, p[0],           a2);
                    ffma2(acc1, p[rstride],     a2);
                    ffma2(acc2, p[2 * rstride], a2);
                    ffma2(acc3, p[3 * rstride], a2);
                }
                float2 f0 = asf2(acc0), f1 = asf2(acc1), f2 = asf2(acc2), f3 = asf2(acc3);
                ulonglong2* oa = reinterpret_cast<ulonglong2*>(s_a + d0 * SP + rb);
                oa[0] = make_ulonglong2(pack2(f0.x), pack2(f1.x));
                oa[1] = make_ulonglong2(pack2(f2.x), pack2(f3.x));
                ulonglong2* ob = reinterpret_cast<ulonglong2*>(s_a + (d0 + 1) * SP + rb);
                ob[0] = make_ulonglong2(pack2(f0.y), pack2(f1.y));
                ob[1] = make_ulonglong2(pack2(f2.y), pack2(f3.y));
            }
            __syncthreads();

            // ---- parent_input = gelu(x @ paW + pab) : 256 -> 256
            split_partial<DM, DM>(s_a, s_red, paW, t);
            __syncthreads();
            reduce_256(s_red, s_b, pab, t);
            __syncthreads();

            // ---- h1 = gelu(parent @ W1 + b1) : 256 -> 128
            split_partial<MM, DM>(s_b, s_red, mW1 + i * DM * MM, t);
            __syncthreads();
            reduce_128(s_red, s_a, mb1 + i * MM, t);
            __syncthreads();

            // ---- h2 = gelu(h1 @ W2 + b2) : 128 -> 128
            split_partial<MM, MM>(s_a, s_red, mW2 + i * MM * MM, t);
            __syncthreads();
            reduce_128(s_red, s_b, mb2 + i * MM, t);
            __syncthreads();

            // ---- o = h2 @ W3 + b3 : 128 -> 256 (partials)
            split_partial<DM, MM>(s_b, s_red, mW3 + i * MM * DM, t);
            __syncthreads();

            // ---- final reduce: + bias + noise -> g_values (+ out on last layer)
            {
                const int fc  = t & 63;           // float4 col group
                const int rp2 = t >> 6;           // rows 2*rp2, 2*rp2+1
                ull sv[2][2];
                #pragma unroll
                for (int cpo = 0; cpo < 2; cpo++) {
                    const int cpG = fc * 2 + cpo;
                    const int cgx = cpG >> 2;
                    const int cpx = cpG & 3;
                    #pragma unroll
                    for (int rr = 0; rr < 2; rr++) {
                        const int r = rp2 * 2 + rr;
                        const ull* p = s_red + ((cpx * 8 + r) * 4) * 32 + cgx;
                        sv[cpo][rr] = fadd2(fadd2(p[0], p[32]), fadd2(p[64], p[96]));
                    }
                }
                const float4 b4 = __ldg(reinterpret_cast<const float4*>(mb3 + i * DM + fc * 4));
                #pragma unroll
                for (int rr = 0; rr < 2; rr++) {
                    const int r = rp2 * 2 + rr;
                    long long gidx = ((long long)(row0 + r) * NV + i) * DM + fc * 4;
                    float4 n4 = __ldg(reinterpret_cast<const float4*>(g_noise + gidx));
                    float2 f0 = asf2(sv[0][rr]);
                    float2 f1 = asf2(sv[1][rr]);
                    float4 v4 = make_float4(f0.x + b4.x + n4.x, f0.y + b4.y + n4.y,
                                            f1.x + b4.z + n4.z, f1.y + b4.w + n4.w);
                    *reinterpret_cast<float4*>(g_values + gidx) = v4;
                    if (last) *reinterpret_cast<float4*>(out + gidx) = v4;
                }
            }
            __syncthreads();
        }
    }
}

// ============================================================================
// Launch
// ============================================================================
#define SCM_SMEM ((4096 + 2560 + 2560 + 1024) * 8)   // 81920 bytes

extern "C" void kernel_launch(void* const* d_in, const int* in_sizes, int n_in,
                              void* d_out, int out_size)
{
    const float* nz   = (const float*)d_in[0];
    const float* elog = (const float*)d_in[1];
    const float* emb  = (const float*)d_in[2];
    const float* paW  = (const float*)d_in[3];
    const float* pab  = (const float*)d_in[4];
    const float* mW1  = (const float*)d_in[5];
    const float* mb1  = (const float*)d_in[6];
    const float* mW2  = (const float*)d_in[7];
    const float* mb2  = (const float*)d_in[8];
    const float* mW3  = (const float*)d_in[9];
    const float* mb3  = (const float*)d_in[10];
    const float* neW  = (const float*)d_in[11];
    const float* neb  = (const float*)d_in[12];
    float* out = (float*)d_out;

    cudaFuncSetAttribute(scm_kernel, cudaFuncAttributeMaxDynamicSharedMemorySize, SCM_SMEM);

    noise_kernel<<<dim3(BATCH / 32, NV), 256>>>(nz, neW, neb);
    scm_kernel<<<NBLK, 256, SCM_SMEM>>>(elog, emb, paW, pab,
                                        mW1, mb1, mW2, mb2, mW3, mb3, out);
}

// round 4
// speedup vs baseline: 2.5883x; 1.2529x over previous
#include <cuda_runtime.h>

// Problem constants
#define NV    32
#define DM    256
#define MM    128
#define DN    64
#define NL    3
#define BATCH 512
#define RPB   4                    // batch rows per block
#define NBLK  (BATCH / RPB)        // 128 blocks
#define SP    6                    // padded row stride (ull) in splat buffers
#define NVDM  (NV * DM)

// Scratch (device global: no allocations allowed)
__device__ float g_noise[BATCH * NV * DM];    // 16 MB: gelu(nz @ ne_W + ne_b)

typedef unsigned long long ull;

// ---- packed f32x2 helpers ----
__device__ __forceinline__ ull pack2(float w) {
    ull r; asm("mov.b64 %0, {%1, %1};" : "=l"(r) : "f"(w)); return r;
}
__device__ __forceinline__ ull pack2f(float a, float b) {
    ull r; asm("mov.b64 %0, {%1, %2};" : "=l"(r) : "f"(a), "f"(b)); return r;
}
__device__ __forceinline__ void ffma2(ull &acc, ull x, ull w) {
    asm("fma.rn.f32x2 %0, %1, %2, %3;" : "=l"(acc) : "l"(x), "l"(w), "l"(acc));
}
__device__ __forceinline__ ull fadd2(ull a, ull b) {
    ull r; asm("add.rn.f32x2 %0, %1, %2;" : "=l"(r) : "l"(a), "l"(b)); return r;
}
__device__ __forceinline__ float2 asf2(ull a) {
    float2 f; asm("mov.b64 {%0, %1}, %2;" : "=f"(f.x), "=f"(f.y) : "l"(a)); return f;
}
__device__ __forceinline__ float gelu(float x) {
    return 0.5f * x * (1.0f + erff(x * 0.7071067811865476f));   // exact erf GELU
}

// ============================================================================
// Kernel 1: noise encoder precompute
// ============================================================================
__global__ void __launch_bounds__(256, 2) noise_kernel(
    const float* __restrict__ nz,    // (B, NV, DN)
    const float* __restrict__ neW,   // (NV, DN, DM)
    const float* __restrict__ neb)   // (NV, DM)
{
    const int i = blockIdx.y;
    const int chunk = blockIdx.x;
    const int d = threadIdx.x;

    __shared__ __align__(16) ull s_nzp[DN][16];
    for (int idx = d; idx < DN * 16; idx += 256) {
        int k = idx >> 4, rp = idx & 15;
        int b = chunk * 32 + rp * 2;
        s_nzp[k][rp] = pack2f(nz[(b * NV + i) * DN + k],
                              nz[((b + 1) * NV + i) * DN + k]);
    }
    __syncthreads();

    ull acc[16];
    #pragma unroll
    for (int rp = 0; rp < 16; rp++) acc[rp] = 0;

    const float* __restrict__ W = neW + i * DN * DM + d;
    #pragma unroll 2
    for (int k = 0; k < DN; k++) {
        ull w2 = pack2(__ldg(W + k * DM));
        const ulonglong2* row = reinterpret_cast<const ulonglong2*>(s_nzp[k]);
        #pragma unroll
        for (int j = 0; j < 8; j++) {
            ulonglong2 x = row[j];
            ffma2(acc[2 * j],     x.x, w2);
            ffma2(acc[2 * j + 1], x.y, w2);
        }
    }
    const float bias = neb[i * DM + d];
    #pragma unroll
    for (int rp = 0; rp < 16; rp++) {
        float2 f = asf2(acc[rp]);
        int b = chunk * 32 + rp * 2;
        g_noise[((long long)b * NV + i) * DM + d]       = gelu(f.x + bias);
        g_noise[((long long)(b + 1) * NV + i) * DM + d] = gelu(f.y + bias);
    }
}

// ============================================================================
// Split-K partial GEMM (RPB=4). Thread owns 8 cols x 2 rows x K-chunk; dup=1.
// red layout: red[((c*4 + r)*KS + ks)*CG + cg]  (partial stores lane-stride-1)
// ============================================================================
template<int N, int K>
__device__ __forceinline__ void split_partial(
    const ull* __restrict__ sin, ull* __restrict__ red,
    const float* __restrict__ W, int t)
{
    constexpr int CG  = N / 8;
    constexpr int LCG = (N == 256) ? 5 : 4;
    constexpr int KS  = 256 >> (LCG + 1);      // 4 (N=256) / 8 (N=128)
    constexpr int CHUNK = K / KS;
    const int cg = t & (CG - 1);
    const int rs = (t >> LCG) & 1;
    const int ks = t >> (LCG + 1);
    const int jg = cg * 8;
    const int r0 = rs * 2;

    ull a[4][2];
    #pragma unroll
    for (int c = 0; c < 4; c++) { a[c][0] = 0; a[c][1] = 0; }

    const ulonglong2* __restrict__ wp =
        reinterpret_cast<const ulonglong2*>(W + (size_t)(ks * CHUNK) * N) + (jg >> 2);
    const ull* __restrict__ xin = sin + (ks * CHUNK) * SP + r0;

    #pragma unroll 8
    for (int d = 0; d < CHUNK; d++) {
        ulonglong2 w0 = __ldg(wp + d * (N / 4));        // cols jg..jg+3
        ulonglong2 w1 = __ldg(wp + d * (N / 4) + 1);    // cols jg+4..jg+7
        ulonglong2 x  = *reinterpret_cast<const ulonglong2*>(xin + d * SP); // rows r0,r0+1
        ffma2(a[0][0], x.x, w0.x); ffma2(a[0][1], x.y, w0.x);
        ffma2(a[1][0], x.x, w0.y); ffma2(a[1][1], x.y, w0.y);
        ffma2(a[2][0], x.x, w1.x); ffma2(a[2][1], x.y, w1.x);
        ffma2(a[3][0], x.x, w1.y); ffma2(a[3][1], x.y, w1.y);
    }
    #pragma unroll
    for (int c = 0; c < 4; c++)
        #pragma unroll
        for (int ri = 0; ri < 2; ri++)
            red[((c * 4 + (r0 + ri)) * KS + ks) * CG + cg] = a[c][ri];
}

// ---- reduce N=256 (KS=4, CG=32): 128 colpairs x 4 rows, 2 rows/thread ----
__device__ __forceinline__ void reduce_256(
    const ull* __restrict__ red, ull* __restrict__ sout,
    const float* __restrict__ bias, int t)
{
    const int cg = t & 31;
    const int c  = (t >> 5) & 3;
    const int rg = t >> 7;                // rows 2rg, 2rg+1
    const int cpG = cg * 4 + c;
    const int col0 = cpG * 2;
    const float2 bb = __ldg(reinterpret_cast<const float2*>(bias) + cpG);
    const ull b2 = pack2f(bb.x, bb.y);
    #pragma unroll
    for (int rr = 0; rr < 2; rr++) {
        const int r = rg * 2 + rr;
        const ull* p = red + ((c * 4 + r) * 4) * 32 + cg;
        ull s = fadd2(fadd2(p[0], p[32]), fadd2(p[64], p[96]));
        s = fadd2(s, b2);
        float2 f = asf2(s);
        sout[col0 * SP + r]       = pack2(gelu(f.x));
        sout[(col0 + 1) * SP + r] = pack2(gelu(f.y));
    }
}

// ---- reduce N=128 (KS=8, CG=16): 64 colpairs x 4 rows, 1/thread ----
__device__ __forceinline__ void reduce_128(
    const ull* __restrict__ red, ull* __restrict__ sout,
    const float* __restrict__ bias, int t)
{
    const int cg = t & 15;
    const int c  = (t >> 4) & 3;
    const int r  = t >> 6;
    const int cpG = cg * 4 + c;
    const int col0 = cpG * 2;
    const float2 bb = __ldg(reinterpret_cast<const float2*>(bias) + cpG);
    const ull b2 = pack2f(bb.x, bb.y);
    const ull* p = red + ((c * 4 + r) * 8) * 16 + cg;
    ull s = fadd2(fadd2(fadd2(p[0], p[16]), fadd2(p[32], p[48])),
                  fadd2(fadd2(p[64], p[80]), fadd2(p[96], p[112])));
    s = fadd2(s, b2);
    float2 f = asf2(s);
    sout[col0 * SP + r]       = pack2(gelu(f.x));
    sout[(col0 + 1) * SP + r] = pack2(gelu(f.y));
}

// ============================================================================
// Main kernel. values live ENTIRELY in smem: s_val[(v*4 + r)*256 + d]
// ============================================================================
__global__ void __launch_bounds__(256, 1) scm_kernel(
    const float* __restrict__ edge_logits,
    const float* __restrict__ var_emb,
    const float* __restrict__ paW,  const float* __restrict__ pab,
    const float* __restrict__ mW1,  const float* __restrict__ mb1,
    const float* __restrict__ mW2,  const float* __restrict__ mb2,
    const float* __restrict__ mW3,  const float* __restrict__ mb3,
    float* __restrict__ out)
{
    extern __shared__ __align__(16) ull smem[];
    ull*   s_red  = smem;                 // 2048 ull = 16KB
    ull*   s_a    = smem + 2048;          // 1536 ull = 12KB (splat [d][r], SP=6)
    ull*   s_b    = smem + 3584;          // 1536 ull = 12KB
    ull*   s_adj2 = smem + 5120;          // 1024 ull =  8KB
    float* s_val  = reinterpret_cast<float*>(smem + 6144);   // 32768 fl = 128KB

    const int t = threadIdx.x;
    const int row0 = blockIdx.x * RPB;

    // adjacency: sigmoid((logits * offdiag)/0.5); diagonal -> 0.5
    for (int idx = t; idx < NV * NV; idx += 256) {
        int ii = idx / NV, v = idx % NV;
        float z = (v == ii) ? 0.0f : edge_logits[v * NV + ii] * 2.0f;
        s_adj2[idx] = pack2(1.0f / (1.0f + expf(-z)));
    }
    __syncthreads();

    for (int layer = 0; layer < NL; layer++) {
        const bool last = (layer == NL - 1);
        for (int i = 0; i < NV; i++) {
            // ---- pc (pure smem): s_a[d][r] = splat(emb[i][d] + sum_v adj*val[v][r][d])
            {
                const int d0 = (t & 127) * 2;
                const int rb = (t >> 7) * 2;      // rows rb, rb+1
                const float2 e = __ldg(reinterpret_cast<const float2*>(var_emb + i * DM + d0));
                ull acc0 = pack2f(e.x, e.y);
                ull acc1 = acc0;
                const float* vp = s_val + rb * DM + d0;
                const int vmax = (layer == 0) ? i : NV;   // layer 0: later vars are zero
                #pragma unroll 4
                for (int v = 0; v < vmax; v++) {
                    ull a2 = s_adj2[i * NV + v];
                    ull x0 = *reinterpret_cast<const ull*>(vp + v * (4 * DM));
                    ull x1 = *reinterpret_cast<const ull*>(vp + v * (4 * DM) + DM);
                    ffma2(acc0, x0, a2);
                    ffma2(acc1, x1, a2);
                }
                float2 f0 = asf2(acc0), f1 = asf2(acc1);
                s_a[d0 * SP + rb]           = pack2(f0.x);
                s_a[d0 * SP + rb + 1]       = pack2(f1.x);
                s_a[(d0 + 1) * SP + rb]     = pack2(f0.y);
                s_a[(d0 + 1) * SP + rb + 1] = pack2(f1.y);
            }
            __syncthreads();

            // ---- parent_input = gelu(x @ paW + pab) : 256 -> 256
            split_partial<DM, DM>(s_a, s_red, paW, t);
            __syncthreads();
            reduce_256(s_red, s_b, pab, t);
            __syncthreads();

            // ---- h1 = gelu(parent @ W1 + b1) : 256 -> 128
            split_partial<MM, DM>(s_b, s_red, mW1 + i * DM * MM, t);
            __syncthreads();
            reduce_128(s_red, s_a, mb1 + i * MM, t);
            __syncthreads();

            // ---- h2 = gelu(h1 @ W2 + b2) : 128 -> 128
            split_partial<MM, MM>(s_a, s_red, mW2 + i * MM * MM, t);
            __syncthreads();
            reduce_128(s_red, s_b, mb2 + i * MM, t);
            __syncthreads();

            // ---- o = h2 @ W3 + b3 : 128 -> 256 (partials)
            split_partial<DM, MM>(s_b, s_red, mW3 + i * MM * DM, t);
            __syncthreads();

            // ---- final: sum partials + bias + noise -> s_val (+ out on last layer)
            {
                const int fc = t & 63;            // float4 col group
                const int r  = t >> 6;            // one row per thread
                ull sv[2];
                #pragma unroll
                for (int cpo = 0; cpo < 2; cpo++) {
                    const int cpG = fc * 2 + cpo;
                    const int cgx = cpG >> 2;
                    const int cpx = cpG & 3;
                    const ull* p = s_red + ((cpx * 4 + r) * 4) * 32 + cgx;
                    sv[cpo] = fadd2(fadd2(p[0], p[32]), fadd2(p[64], p[96]));
                }
                const float4 b4 = __ldg(reinterpret_cast<const float4*>(mb3 + i * DM + fc * 4));
                long long gidx = ((long long)(row0 + r) * NV + i) * DM + fc * 4;
                float4 n4 = __ldg(reinterpret_cast<const float4*>(g_noise + gidx));
                float2 f0 = asf2(sv[0]);
                float2 f1 = asf2(sv[1]);
                float4 v4 = make_float4(f0.x + b4.x + n4.x, f0.y + b4.y + n4.y,
                                        f1.x + b4.z + n4.z, f1.y + b4.w + n4.w);
                *reinterpret_cast<float4*>(s_val + (i * 4 + r) * DM + fc * 4) = v4;
                if (last) *reinterpret_cast<float4*>(out + gidx) = v4;
            }
            __syncthreads();
        }
    }
}

// ============================================================================
// Launch
// ============================================================================
#define SCM_SMEM ((6144 + 16384) * 8)   // 180224 bytes = 176KB

extern "C" void kernel_launch(void* const* d_in, const int* in_sizes, int n_in,
                              void* d_out, int out_size)
{
    const float* nz   = (const float*)d_in[0];
    const float* elog = (const float*)d_in[1];
    const float* emb  = (const float*)d_in[2];
    const float* paW  = (const float*)d_in[3];
    const float* pab  = (const float*)d_in[4];
    const float* mW1  = (const float*)d_in[5];
    const float* mb1  = (const float*)d_in[6];
    const float* mW2  = (const float*)d_in[7];
    const float* mb2  = (const float*)d_in[8];
    const float* mW3  = (const float*)d_in[9];
    const float* mb3  = (const float*)d_in[10];
    const float* neW  = (const float*)d_in[11];
    const float* neb  = (const float*)d_in[12];
    float* out = (float*)d_out;

    cudaFuncSetAttribute(scm_kernel, cudaFuncAttributeMaxDynamicSharedMemorySize, SCM_SMEM);

    noise_kernel<<<dim3(BATCH / 32, NV), 256>>>(nz, neW, neb);
    scm_kernel<<<NBLK, 256, SCM_SMEM>>>(elog, emb, paW, pab,
                                        mW1, mb1, mW2, mb2, mW3, mb3, out);
}

// round 5
// speedup vs baseline: 2.5957x; 1.0029x over previous
#include <cuda_runtime.h>

// Problem constants
#define NV    32
#define DM    256
#define MM    128
#define DN    64
#define NL    3
#define BATCH 512
#define RPB   4                    // batch rows per block
#define NBLK  (BATCH / RPB)        // 128 blocks
#define NT    512                  // threads per block
#define SROW  258                  // splat buffer row stride (ull), even
#define NVDM  (NV * DM)

// Scratch (device global: no allocations allowed)
__device__ float g_noise[BATCH * NV * DM];    // 16 MB: gelu(nz @ ne_W + ne_b)

typedef unsigned long long ull;

// ---- packed f32x2 helpers ----
__device__ __forceinline__ ull pack2(float w) {
    ull r; asm("mov.b64 %0, {%1, %1};" : "=l"(r) : "f"(w)); return r;
}
__device__ __forceinline__ ull pack2f(float a, float b) {
    ull r; asm("mov.b64 %0, {%1, %2};" : "=l"(r) : "f"(a), "f"(b)); return r;
}
__device__ __forceinline__ void ffma2(ull &acc, ull x, ull w) {
    asm("fma.rn.f32x2 %0, %1, %2, %3;" : "=l"(acc) : "l"(x), "l"(w), "l"(acc));
}
__device__ __forceinline__ ull fadd2(ull a, ull b) {
    ull r; asm("add.rn.f32x2 %0, %1, %2;" : "=l"(r) : "l"(a), "l"(b)); return r;
}
__device__ __forceinline__ float2 asf2(ull a) {
    float2 f; asm("mov.b64 {%0, %1}, %2;" : "=f"(f.x), "=f"(f.y) : "l"(a)); return f;
}
__device__ __forceinline__ float gelu(float x) {
    return 0.5f * x * (1.0f + erff(x * 0.7071067811865476f));   // exact erf GELU
}

// ============================================================================
// Kernel 1: noise encoder precompute
// ============================================================================
__global__ void __launch_bounds__(256, 2) noise_kernel(
    const float* __restrict__ nz,    // (B, NV, DN)
    const float* __restrict__ neW,   // (NV, DN, DM)
    const float* __restrict__ neb)   // (NV, DM)
{
    const int i = blockIdx.y;
    const int chunk = blockIdx.x;
    const int d = threadIdx.x;

    __shared__ __align__(16) ull s_nzp[DN][16];
    for (int idx = d; idx < DN * 16; idx += 256) {
        int k = idx >> 4, rp = idx & 15;
        int b = chunk * 32 + rp * 2;
        s_nzp[k][rp] = pack2f(nz[(b * NV + i) * DN + k],
                              nz[((b + 1) * NV + i) * DN + k]);
    }
    __syncthreads();

    ull acc[16];
    #pragma unroll
    for (int rp = 0; rp < 16; rp++) acc[rp] = 0;

    const float* __restrict__ W = neW + i * DN * DM + d;
    #pragma unroll 2
    for (int k = 0; k < DN; k++) {
        ull w2 = pack2(__ldg(W + k * DM));
        const ulonglong2* row = reinterpret_cast<const ulonglong2*>(s_nzp[k]);
        #pragma unroll
        for (int j = 0; j < 8; j++) {
            ulonglong2 x = row[j];
            ffma2(acc[2 * j],     x.x, w2);
            ffma2(acc[2 * j + 1], x.y, w2);
        }
    }
    const float bias = neb[i * DM + d];
    #pragma unroll
    for (int rp = 0; rp < 16; rp++) {
        float2 f = asf2(acc[rp]);
        int b = chunk * 32 + rp * 2;
        g_noise[((long long)b * NV + i) * DM + d]       = gelu(f.x + bias);
        g_noise[((long long)(b + 1) * NV + i) * DM + d] = gelu(f.y + bias);
    }
}

// ============================================================================
// Split-K partial GEMM (512 threads). Thread owns 8 cols x 2 rows x K-chunk.
// Splat buffers are row-major: sin[r*SROW + d] = splat of x[r][d].
// red layout: red[((c*4 + r)*KS + ks)*CG + cg]  (lane-stride-1 stores)
// ============================================================================
template<int N, int K>
__device__ __forceinline__ void split_partial(
    const ull* __restrict__ sin, ull* __restrict__ red,
    const float* __restrict__ W, int t)
{
    constexpr int CG  = N / 8;
    constexpr int LCG = (N == 256) ? 5 : 4;
    constexpr int KS  = NT >> (LCG + 1);       // 8 (N=256) / 16 (N=128)
    constexpr int CHUNK = K / KS;
    const int cg = t & (CG - 1);
    const int rs = (t >> LCG) & 1;
    const int ks = t >> (LCG + 1);
    const int jg = cg * 8;
    const int r0 = rs * 2;

    ull a[4][2];
    #pragma unroll
    for (int c = 0; c < 4; c++) { a[c][0] = 0; a[c][1] = 0; }

    const ulonglong2* __restrict__ wp =
        reinterpret_cast<const ulonglong2*>(W + (size_t)(ks * CHUNK) * N) + (jg >> 2);
    const ull* __restrict__ x0p = sin + r0 * SROW + ks * CHUNK;
    const ull* __restrict__ x1p = x0p + SROW;

    #pragma unroll
    for (int d = 0; d < CHUNK; d++) {
        ulonglong2 w0 = __ldg(wp + d * (N / 4));        // cols jg..jg+3
        ulonglong2 w1 = __ldg(wp + d * (N / 4) + 1);    // cols jg+4..jg+7
        ull x0 = x0p[d];                                // broadcast LDS.64
        ull x1 = x1p[d];
        ffma2(a[0][0], x0, w0.x); ffma2(a[0][1], x1, w0.x);
        ffma2(a[1][0], x0, w0.y); ffma2(a[1][1], x1, w0.y);
        ffma2(a[2][0], x0, w1.x); ffma2(a[2][1], x1, w1.x);
        ffma2(a[3][0], x0, w1.y); ffma2(a[3][1], x1, w1.y);
    }
    #pragma unroll
    for (int c = 0; c < 4; c++)
        #pragma unroll
        for (int ri = 0; ri < 2; ri++)
            red[((c * 4 + (r0 + ri)) * KS + ks) * CG + cg] = a[c][ri];
}

// ---- reduce N=256 (KS=8, CG=32): thread = (colpair cpG, row r), 512 items ----
__device__ __forceinline__ void reduce_256(
    const ull* __restrict__ red, ull* __restrict__ sout,
    const float* __restrict__ bias, int t)
{
    const int cpG = t & 127;
    const int r   = t >> 7;
    const int cgx = cpG >> 2, cpx = cpG & 3;
    const float2 bb = __ldg(reinterpret_cast<const float2*>(bias) + cpG);
    const ull* p = red + ((cpx * 4 + r) * 8) * 32 + cgx;
    ull s = fadd2(fadd2(fadd2(p[0],     p[32]),  fadd2(p[64],  p[96])),
                  fadd2(fadd2(p[128],   p[160]), fadd2(p[192], p[224])));
    s = fadd2(s, pack2f(bb.x, bb.y));
    float2 f = asf2(s);
    // conflict-free STS.128: lanes write consecutive 16B
    *reinterpret_cast<ulonglong2*>(sout + r * SROW + cpG * 2) =
        make_ulonglong2(pack2(gelu(f.x)), pack2(gelu(f.y)));
}

// ---- reduce N=128 (KS=16, CG=16): 256 items; threads t<256 only ----
__device__ __forceinline__ void reduce_128(
    const ull* __restrict__ red, ull* __restrict__ sout,
    const float* __restrict__ bias, int t)
{
    const int cpG = t & 63;
    const int r   = t >> 6;
    const int cgx = cpG >> 2, cpx = cpG & 3;
    const float2 bb = __ldg(reinterpret_cast<const float2*>(bias) + cpG);
    const ull* p = red + ((cpx * 4 + r) * 16) * 16 + cgx;
    ull s = 0;
    #pragma unroll
    for (int k = 0; k < 16; k += 4)
        s = fadd2(s, fadd2(fadd2(p[16 * k], p[16 * (k + 1)]),
                           fadd2(p[16 * (k + 2)], p[16 * (k + 3)])));
    s = fadd2(s, pack2f(bb.x, bb.y));
    float2 f = asf2(s);
    *reinterpret_cast<ulonglong2*>(sout + r * SROW + cpG * 2) =
        make_ulonglong2(pack2(gelu(f.x)), pack2(gelu(f.y)));
}

// ============================================================================
// Main kernel. values live ENTIRELY in smem: s_val[(v*4 + r)*256 + d]
// ============================================================================
__global__ void __launch_bounds__(NT, 1) scm_kernel(
    const float* __restrict__ edge_logits,
    const float* __restrict__ var_emb,
    const float* __restrict__ paW,  const float* __restrict__ pab,
    const float* __restrict__ mW1,  const float* __restrict__ mb1,
    const float* __restrict__ mW2,  const float* __restrict__ mb2,
    const float* __restrict__ mW3,  const float* __restrict__ mb3,
    float* __restrict__ out)
{
    extern __shared__ __align__(16) ull smem[];
    ull*   s_red  = smem;                 // 4096 ull = 32KB
    ull*   s_a    = smem + 4096;          // 1032 ull (4 rows x SROW)
    ull*   s_b    = smem + 5128;          // 1032 ull
    ull*   s_adj2 = smem + 6160;          // 1024 ull = 8KB
    float* s_val  = reinterpret_cast<float*>(smem + 7184);   // 32768 fl = 128KB

    const int t = threadIdx.x;
    const int row0 = blockIdx.x * RPB;

    // adjacency: sigmoid((logits * offdiag)/0.5); diagonal -> 0.5
    for (int idx = t; idx < NV * NV; idx += NT) {
        int ii = idx / NV, v = idx % NV;
        float z = (v == ii) ? 0.0f : edge_logits[v * NV + ii] * 2.0f;
        s_adj2[idx] = pack2(1.0f / (1.0f + expf(-z)));
    }
    __syncthreads();

    for (int layer = 0; layer < NL; layer++) {
        const bool last = (layer == NL - 1);
        for (int i = 0; i < NV; i++) {
            // ---- pc (pure smem): s_a[r][d] = splat(emb[i][d] + sum_v adj*val[v][r][d])
            {
                const int d0 = (t & 127) * 2;
                const int r  = t >> 7;
                const float2 e = __ldg(reinterpret_cast<const float2*>(var_emb + i * DM + d0));
                ull acc = pack2f(e.x, e.y);
                const float* vp = s_val + r * DM + d0;
                const int vmax = (layer == 0) ? i : NV;   // layer 0: later vars zero
                #pragma unroll 4
                for (int v = 0; v < vmax; v++) {
                    ull a2 = s_adj2[i * NV + v];
                    ull x  = *reinterpret_cast<const ull*>(vp + v * (4 * DM));
                    ffma2(acc, x, a2);
                }
                float2 f = asf2(acc);
                *reinterpret_cast<ulonglong2*>(s_a + r * SROW + d0) =
                    make_ulonglong2(pack2(f.x), pack2(f.y));
            }
            __syncthreads();

            // ---- parent_input = gelu(x @ paW + pab) : 256 -> 256
            split_partial<DM, DM>(s_a, s_red, paW, t);
            __syncthreads();
            reduce_256(s_red, s_b, pab, t);
            __syncthreads();

            // ---- h1 = gelu(parent @ W1 + b1) : 256 -> 128
            split_partial<MM, DM>(s_b, s_red, mW1 + i * DM * MM, t);
            __syncthreads();
            if (t < 256) reduce_128(s_red, s_a, mb1 + i * MM, t);
            __syncthreads();

            // ---- h2 = gelu(h1 @ W2 + b2) : 128 -> 128
            split_partial<MM, MM>(s_a, s_red, mW2 + i * MM * MM, t);
            __syncthreads();
            if (t < 256) reduce_128(s_red, s_b, mb2 + i * MM, t);
            __syncthreads();

            // ---- o = h2 @ W3 + b3 : 128 -> 256 (partials)
            split_partial<DM, MM>(s_b, s_red, mW3 + i * MM * DM, t);
            __syncthreads();

            // ---- final: sum partials + bias + noise -> s_val (+ out on last layer)
            {
                const int cpG = t & 127;          // float2 col group
                const int r   = t >> 7;
                const int cgx = cpG >> 2, cpx = cpG & 3;
                const ull* p = s_red + ((cpx * 4 + r) * 8) * 32 + cgx;
                ull s = fadd2(fadd2(fadd2(p[0],   p[32]),  fadd2(p[64],  p[96])),
                              fadd2(fadd2(p[128], p[160]), fadd2(p[192], p[224])));
                const float2 b2 = __ldg(reinterpret_cast<const float2*>(mb3 + i * DM) + cpG);
                long long gidx = ((long long)(row0 + r) * NV + i) * DM + cpG * 2;
                const float2 n2 = *reinterpret_cast<const float2*>(g_noise + gidx);
                float2 f = asf2(s);
                float2 v2 = make_float2(f.x + b2.x + n2.x, f.y + b2.y + n2.y);
                *reinterpret_cast<float2*>(s_val + (i * 4 + r) * DM + cpG * 2) = v2;
                if (last) *reinterpret_cast<float2*>(out + gidx) = v2;
            }
            __syncthreads();
        }
    }
}

// ============================================================================
// Launch
// ============================================================================
#define SCM_SMEM ((7184 + 16384) * 8)   // 188544 bytes

extern "C" void kernel_launch(void* const* d_in, const int* in_sizes, int n_in,
                              void* d_out, int out_size)
{
    const float* nz   = (const float*)d_in[0];
    const float* elog = (const float*)d_in[1];
    const float* emb  = (const float*)d_in[2];
    const float* paW  = (const float*)d_in[3];
    const float* pab  = (const float*)d_in[4];
    const float* mW1  = (const float*)d_in[5];
    const float* mb1  = (const float*)d_in[6];
    const float* mW2  = (const float*)d_in[7];
    const float* mb2  = (const float*)d_in[8];
    const float* mW3  = (const float*)d_in[9];
    const float* mb3  = (const float*)d_in[10];
    const float* neW  = (const float*)d_in[11];
    const float* neb  = (const float*)d_in[12];
    float* out = (float*)d_out;

    cudaFuncSetAttribute(scm_kernel, cudaFuncAttributeMaxDynamicSharedMemorySize, SCM_SMEM);

    noise_kernel<<<dim3(BATCH / 32, NV), 256>>>(nz, neW, neb);
    scm_kernel<<<NBLK, NT, SCM_SMEM>>>(elog, emb, paW, pab,
                                       mW1, mb1, mW2, mb2, mW3, mb3, out);
}

// round 6
// speedup vs baseline: 4.3378x; 1.6712x over previous
#include <cuda_runtime.h>

// Problem constants
#define NV    32
#define DM    256
#define MM    128
#define DN    64
#define NL    3
#define BATCH 512
#define RPB   4                    // batch rows per block
#define NBLK  (BATCH / RPB)        // 128 blocks
#define NT    512                  // threads per block
#define AROW  130                  // activation buffer row stride (ull = float2)

// Scratch (device globals: no allocations allowed)
__device__ float g_noise[BATCH * NV * DM];       // 16 MB: gelu(nz @ ne_W + ne_b)
__device__ float g_wpack[2686976];               // parity-packed weights, 10.7 MB

// offsets into g_wpack (floats)
#define OFF_PA  0                          // paW: 256x256          -> 65536
#define OFF_W1  65536                      // 32 x (256x128=32768)  -> 1048576
#define OFF_W2  1114112                    // 32 x (128x128=16384)  -> 524288
#define OFF_W3  1638400                    // 32 x (128x256=32768)  -> 1048576

typedef unsigned long long ull;

// ---- packed f32x2 helpers ----
__device__ __forceinline__ ull pack2(float w) {
    ull r; asm("mov.b64 %0, {%1, %1};" : "=l"(r) : "f"(w)); return r;
}
__device__ __forceinline__ ull pack2f(float a, float b) {
    ull r; asm("mov.b64 %0, {%1, %2};" : "=l"(r) : "f"(a), "f"(b)); return r;
}
__device__ __forceinline__ void ffma2(ull &acc, ull x, ull w) {
    asm("fma.rn.f32x2 %0, %1, %2, %3;" : "=l"(acc) : "l"(x), "l"(w), "l"(acc));
}
__device__ __forceinline__ ull fadd2(ull a, ull b) {
    ull r; asm("add.rn.f32x2 %0, %1, %2;" : "=l"(r) : "l"(a), "l"(b)); return r;
}
__device__ __forceinline__ float2 asf2(ull a) {
    float2 f; asm("mov.b64 {%0, %1}, %2;" : "=f"(f.x), "=f"(f.y) : "l"(a)); return f;
}
__device__ __forceinline__ float lanesum(ull a) {
    float2 f = asf2(a); return f.x + f.y;
}
__device__ __forceinline__ float gelu(float x) {
    return 0.5f * x * (1.0f + erff(x * 0.7071067811865476f));   // exact erf GELU
}

// ============================================================================
// Weight pack kernel: Wp[d2][parity][N] <- W[k][N], k = 2*d2 + parity
// ============================================================================
template<int K, int N>
__global__ void pack_kernel(float* __restrict__ dst, const float* __restrict__ src)
{
    const int var = blockIdx.y;
    const float* __restrict__ s = src + (size_t)var * K * N;
    float* __restrict__ d = dst + (size_t)var * K * N;
    for (int idx = blockIdx.x * blockDim.x + threadIdx.x; idx < K * N;
         idx += gridDim.x * blockDim.x) {
        int d2  = idx / (2 * N);
        int rem = idx - d2 * (2 * N);
        int p   = rem / N;
        int j   = rem - p * N;
        d[idx] = s[(2 * d2 + p) * N + j];
    }
}

// ============================================================================
// Kernel: noise encoder precompute
// ============================================================================
__global__ void __launch_bounds__(256, 2) noise_kernel(
    const float* __restrict__ nz,    // (B, NV, DN)
    const float* __restrict__ neW,   // (NV, DN, DM)
    const float* __restrict__ neb)   // (NV, DM)
{
    const int i = blockIdx.y;
    const int chunk = blockIdx.x;
    const int d = threadIdx.x;

    __shared__ __align__(16) ull s_nzp[DN][16];
    for (int idx = d; idx < DN * 16; idx += 256) {
        int k = idx >> 4, rp = idx & 15;
        int b = chunk * 32 + rp * 2;
        s_nzp[k][rp] = pack2f(nz[(b * NV + i) * DN + k],
                              nz[((b + 1) * NV + i) * DN + k]);
    }
    __syncthreads();

    ull acc[16];
    #pragma unroll
    for (int rp = 0; rp < 16; rp++) acc[rp] = 0;

    const float* __restrict__ W = neW + i * DN * DM + d;
    #pragma unroll 2
    for (int k = 0; k < DN; k++) {
        ull w2 = pack2(__ldg(W + k * DM));
        const ulonglong2* row = reinterpret_cast<const ulonglong2*>(s_nzp[k]);
        #pragma unroll
        for (int j = 0; j < 8; j++) {
            ulonglong2 x = row[j];
            ffma2(acc[2 * j],     x.x, w2);
            ffma2(acc[2 * j + 1], x.y, w2);
        }
    }
    const float bias = neb[i * DM + d];
    #pragma unroll
    for (int rp = 0; rp < 16; rp++) {
        float2 f = asf2(acc[rp]);
        int b = chunk * 32 + rp * 2;
        g_noise[((long long)b * NV + i) * DM + d]       = gelu(f.x + bias);
        g_noise[((long long)(b + 1) * NV + i) * DM + d] = gelu(f.y + bias);
    }
}

// ============================================================================
// Split-K partial GEMM, K-parity packed. Thread = (cg, ks): 4 cols x 4 rows.
// dup=1 weight loads (dense LDG.128 x2 / iter), activation = 1 broadcast
// LDS.64 per (row, K-pair). Partials: red[(r*KS+ks)*N + j], dense STS.128.
// ============================================================================
template<int N, int K>
__device__ __forceinline__ void split_partial(
    const ull* __restrict__ sinu,       // activation [r][d2] (float2 as ull)
    float* __restrict__ red,
    const float* __restrict__ Wp, int t)
{
    constexpr int CG = N / 4;           // 64 (N=256) / 32 (N=128)
    constexpr int KS = NT / CG;         // 8 / 16
    constexpr int D2 = (K / KS) / 2;    // K-pairs per thread
    const int cg = t & (CG - 1);
    const int ks = t / CG;
    const int j0 = cg * 4;

    ull acc[4][4];                      // [col][row], lanes = even/odd K partials
    #pragma unroll
    for (int c = 0; c < 4; c++)
        #pragma unroll
        for (int r = 0; r < 4; r++) acc[c][r] = 0;

    const float4* __restrict__ wE =
        reinterpret_cast<const float4*>(Wp + (size_t)(ks * D2) * (2 * N) + j0);
    const float4* __restrict__ wO =
        reinterpret_cast<const float4*>(Wp + (size_t)(ks * D2) * (2 * N) + N + j0);
    const ull* __restrict__ x = sinu + ks * D2;

    #pragma unroll 8
    for (int d = 0; d < D2; d++) {
        float4 we = __ldg(wE + d * (N / 2));
        float4 wo = __ldg(wO + d * (N / 2));
        ull w0 = pack2f(we.x, wo.x);
        ull w1 = pack2f(we.y, wo.y);
        ull w2 = pack2f(we.z, wo.z);
        ull w3 = pack2f(we.w, wo.w);
        #pragma unroll
        for (int r = 0; r < 4; r++) {
            ull xv = x[r * AROW + d];           // broadcast LDS.64: (x_even, x_odd)
            ffma2(acc[0][r], xv, w0);
            ffma2(acc[1][r], xv, w1);
            ffma2(acc[2][r], xv, w2);
            ffma2(acc[3][r], xv, w3);
        }
    }
    #pragma unroll
    for (int r = 0; r < 4; r++) {
        float4 o = make_float4(lanesum(acc[0][r]), lanesum(acc[1][r]),
                               lanesum(acc[2][r]), lanesum(acc[3][r]));
        *reinterpret_cast<float4*>(red + (r * KS + ks) * N + j0) = o;
    }
}

// ---- reduce partials -> gelu -> activation buffer (float2 rows) ----
// N=256: 512 threads (j2 = t&127, r = t>>7), KS=8
// N=128: 256 threads (j2 = t&63,  r = t>>6), KS=16
template<int N>
__device__ __forceinline__ void reduce_act(
    const float* __restrict__ red, ull* __restrict__ soutu,
    const float* __restrict__ bias, int t)
{
    constexpr int KS = 2048 / N;
    constexpr int J2 = N / 2;
    const int j2 = t & (J2 - 1);
    const int r  = (N == 256) ? (t >> 7) : (t >> 6);
    const ull* __restrict__ rp = reinterpret_cast<const ull*>(red);
    ull s = 0;
    #pragma unroll
    for (int k = 0; k < KS; k++)
        s = fadd2(s, rp[(r * KS + k) * J2 + j2]);
    const float2 bb = __ldg(reinterpret_cast<const float2*>(bias) + j2);
    s = fadd2(s, pack2f(bb.x, bb.y));
    float2 f = asf2(s);
    soutu[r * AROW + j2] = pack2f(gelu(f.x), gelu(f.y));
}

// ============================================================================
// Main kernel. values live in smem: s_val[(v*4 + r)*256 + d] (float)
// ============================================================================
__global__ void __launch_bounds__(NT, 1) scm_kernel(
    const float* __restrict__ edge_logits,
    const float* __restrict__ var_emb,
    const float* __restrict__ pab,
    const float* __restrict__ mb1,
    const float* __restrict__ mb2,
    const float* __restrict__ mb3,
    float* __restrict__ out)
{
    extern __shared__ __align__(16) ull smem[];
    float* s_red  = reinterpret_cast<float*>(smem);          // 8192 fl = 32KB
    ull*   s_a    = smem + 4096;                             // 520 ull (4 x AROW)
    ull*   s_b    = smem + 4616;                             // 520 ull
    ull*   s_adj2 = smem + 5136;                             // 1024 ull = 8KB
    float* s_val  = reinterpret_cast<float*>(smem + 6160);   // 32768 fl = 128KB

    const int t = threadIdx.x;
    const int row0 = blockIdx.x * RPB;

    // adjacency: sigmoid((logits * offdiag)/0.5); diagonal -> 0.5 (splat ull)
    for (int idx = t; idx < NV * NV; idx += NT) {
        int ii = idx / NV, v = idx % NV;
        float z = (v == ii) ? 0.0f : edge_logits[v * NV + ii] * 2.0f;
        s_adj2[idx] = pack2(1.0f / (1.0f + expf(-z)));
    }
    __syncthreads();

    for (int layer = 0; layer < NL; layer++) {
        const bool last = (layer == NL - 1);
        for (int i = 0; i < NV; i++) {
            // ---- pc: s_a[r][d2] = (emb + sum_v adj * val)[2 dims]  (pure smem)
            {
                const int d2 = t & 127;
                const int r  = t >> 7;
                const int d0 = d2 * 2;
                const float2 e = __ldg(reinterpret_cast<const float2*>(var_emb + i * DM + d0));
                ull acc = pack2f(e.x, e.y);
                const float* vp = s_val + r * DM + d0;
                const int vmax = (layer == 0) ? i : NV;   // layer 0: later vars zero
                #pragma unroll 4
                for (int v = 0; v < vmax; v++) {
                    ull a2 = s_adj2[i * NV + v];
                    ull x  = *reinterpret_cast<const ull*>(vp + v * (4 * DM));
                    ffma2(acc, x, a2);
                }
                s_a[r * AROW + d2] = acc;
            }
            __syncthreads();

            // ---- parent_input = gelu(x @ paW + pab) : 256 -> 256
            split_partial<DM, DM>(s_a, s_red, g_wpack + OFF_PA, t);
            __syncthreads();
            reduce_act<DM>(s_red, s_b, pab, t);
            __syncthreads();

            // ---- h1 = gelu(parent @ W1 + b1) : 256 -> 128
            split_partial<MM, DM>(s_b, s_red, g_wpack + OFF_W1 + i * (DM * MM), t);
            __syncthreads();
            if (t < 256) reduce_act<MM>(s_red, s_a, mb1 + i * MM, t);
            __syncthreads();

            // ---- h2 = gelu(h1 @ W2 + b2) : 128 -> 128
            split_partial<MM, MM>(s_a, s_red, g_wpack + OFF_W2 + i * (MM * MM), t);
            __syncthreads();
            if (t < 256) reduce_act<MM>(s_red, s_b, mb2 + i * MM, t);
            __syncthreads();

            // ---- o = h2 @ W3 + b3 : 128 -> 256 (partials)
            split_partial<DM, MM>(s_b, s_red, g_wpack + OFF_W3 + i * (MM * DM), t);
            __syncthreads();

            // ---- final: sum partials + bias + noise -> s_val (+ out on last)
            {
                const int j2 = t & 127;
                const int r  = t >> 7;
                const ull* rp = reinterpret_cast<const ull*>(s_red);
                ull s = 0;
                #pragma unroll
                for (int k = 0; k < 8; k++)
                    s = fadd2(s, rp[(r * 8 + k) * 128 + j2]);
                const float2 b2 = __ldg(reinterpret_cast<const float2*>(mb3 + i * DM) + j2);
                long long gidx = ((long long)(row0 + r) * NV + i) * DM + j2 * 2;
                const float2 n2 = __ldg(reinterpret_cast<const float2*>(g_noise + gidx));
                float2 f = asf2(s);
                float2 v2 = make_float2(f.x + b2.x + n2.x, f.y + b2.y + n2.y);
                *reinterpret_cast<float2*>(s_val + (i * 4 + r) * DM + j2 * 2) = v2;
                if (last) *reinterpret_cast<float2*>(out + gidx) = v2;
            }
            __syncthreads();
        }
    }
}

// ============================================================================
// Launch
// ============================================================================
#define SCM_SMEM ((6160 + 16384) * 8)   // 180352 bytes

extern "C" void kernel_launch(void* const* d_in, const int* in_sizes, int n_in,
                              void* d_out, int out_size)
{
    const float* nz   = (const float*)d_in[0];
    const float* elog = (const float*)d_in[1];
    const float* emb  = (const float*)d_in[2];
    const float* paW  = (const float*)d_in[3];
    const float* pab  = (const float*)d_in[4];
    const float* mW1  = (const float*)d_in[5];
    const float* mb1  = (const float*)d_in[6];
    const float* mW2  = (const float*)d_in[7];
    const float* mb2  = (const float*)d_in[8];
    const float* mW3  = (const float*)d_in[9];
    const float* mb3  = (const float*)d_in[10];
    const float* neW  = (const float*)d_in[11];
    const float* neb  = (const float*)d_in[12];
    float* out = (float*)d_out;

    static float* wp = nullptr;
    if (!wp) cudaGetSymbolAddress((void**)&wp, g_wpack);

    cudaFuncSetAttribute(scm_kernel, cudaFuncAttributeMaxDynamicSharedMemorySize, SCM_SMEM);

    pack_kernel<DM, DM><<<dim3(64, 1),  256>>>(wp + OFF_PA, paW);
    pack_kernel<DM, MM><<<dim3(32, NV), 256>>>(wp + OFF_W1, mW1);
    pack_kernel<MM, MM><<<dim3(16, NV), 256>>>(wp + OFF_W2, mW2);
    pack_kernel<MM, DM><<<dim3(32, NV), 256>>>(wp + OFF_W3, mW3);
    noise_kernel<<<dim3(BATCH / 32, NV), 256>>>(nz, neW, neb);
    scm_kernel<<<NBLK, NT, SCM_SMEM>>>(elog, emb, pab, mb1, mb2, mb3, out);
}

// round 7
// speedup vs baseline: 4.4823x; 1.0333x over previous
#include <cuda_runtime.h>

// Problem constants
#define NV    32
#define DM    256
#define MM    128
#define DN    64
#define NL    3
#define BATCH 512
#define RPB   4                    // batch rows per block
#define NBLK  (BATCH / RPB)        // 128 blocks
#define NT    512                  // threads per block
#define AROW  130                  // activation buffer row stride (ull = float2)

// Scratch (device globals: no allocations allowed)
__device__ float g_noise[BATCH * NV * DM];       // 16 MB: gelu(nz @ ne_W + ne_b)
__device__ float g_wpack[2686976];               // parity-packed weights, 10.7 MB

// offsets into g_wpack (floats)
#define OFF_PA  0
#define OFF_W1  65536
#define OFF_W2  1114112
#define OFF_W3  1638400

typedef unsigned long long ull;

// ---- packed f32x2 helpers ----
__device__ __forceinline__ ull pack2(float w) {
    ull r; asm("mov.b64 %0, {%1, %1};" : "=l"(r) : "f"(w)); return r;
}
__device__ __forceinline__ ull pack2f(float a, float b) {
    ull r; asm("mov.b64 %0, {%1, %2};" : "=l"(r) : "f"(a), "f"(b)); return r;
}
__device__ __forceinline__ void ffma2(ull &acc, ull x, ull w) {
    asm("fma.rn.f32x2 %0, %1, %2, %3;" : "=l"(acc) : "l"(x), "l"(w), "l"(acc));
}
__device__ __forceinline__ ull fadd2(ull a, ull b) {
    ull r; asm("add.rn.f32x2 %0, %1, %2;" : "=l"(r) : "l"(a), "l"(b)); return r;
}
__device__ __forceinline__ float2 asf2(ull a) {
    float2 f; asm("mov.b64 {%0, %1}, %2;" : "=f"(f.x), "=f"(f.y) : "l"(a)); return f;
}
__device__ __forceinline__ float lanesum(ull a) {
    float2 f = asf2(a); return f.x + f.y;
}
__device__ __forceinline__ float gelu(float x) {
    return 0.5f * x * (1.0f + erff(x * 0.7071067811865476f));   // exact erf GELU
}

// ============================================================================
// Weight pack kernel: Wp[d2][parity][N] <- W[k][N], k = 2*d2 + parity
// ============================================================================
template<int K, int N>
__global__ void pack_kernel(float* __restrict__ dst, const float* __restrict__ src)
{
    const int var = blockIdx.y;
    const float* __restrict__ s = src + (size_t)var * K * N;
    float* __restrict__ d = dst + (size_t)var * K * N;
    for (int idx = blockIdx.x * blockDim.x + threadIdx.x; idx < K * N;
         idx += gridDim.x * blockDim.x) {
        int d2  = idx / (2 * N);
        int rem = idx - d2 * (2 * N);
        int p   = rem / N;
        int j   = rem - p * N;
        d[idx] = s[(2 * d2 + p) * N + j];
    }
}

// ============================================================================
// Kernel: noise encoder precompute
// ============================================================================
__global__ void __launch_bounds__(256, 2) noise_kernel(
    const float* __restrict__ nz,
    const float* __restrict__ neW,
    const float* __restrict__ neb)
{
    const int i = blockIdx.y;
    const int chunk = blockIdx.x;
    const int d = threadIdx.x;

    __shared__ __align__(16) ull s_nzp[DN][16];
    for (int idx = d; idx < DN * 16; idx += 256) {
        int k = idx >> 4, rp = idx & 15;
        int b = chunk * 32 + rp * 2;
        s_nzp[k][rp] = pack2f(nz[(b * NV + i) * DN + k],
                              nz[((b + 1) * NV + i) * DN + k]);
    }
    __syncthreads();

    ull acc[16];
    #pragma unroll
    for (int rp = 0; rp < 16; rp++) acc[rp] = 0;

    const float* __restrict__ W = neW + i * DN * DM + d;
    #pragma unroll 2
    for (int k = 0; k < DN; k++) {
        ull w2 = pack2(__ldg(W + k * DM));
        const ulonglong2* row = reinterpret_cast<const ulonglong2*>(s_nzp[k]);
        #pragma unroll
        for (int j = 0; j < 8; j++) {
            ulonglong2 x = row[j];
            ffma2(acc[2 * j],     x.x, w2);
            ffma2(acc[2 * j + 1], x.y, w2);
        }
    }
    const float bias = neb[i * DM + d];
    #pragma unroll
    for (int rp = 0; rp < 16; rp++) {
        float2 f = asf2(acc[rp]);
        int b = chunk * 32 + rp * 2;
        g_noise[((long long)b * NV + i) * DM + d]       = gelu(f.x + bias);
        g_noise[((long long)(b + 1) * NV + i) * DM + d] = gelu(f.y + bias);
    }
}

// ============================================================================
// Split-K partial GEMM, K-parity packed. Thread = (cg, ks): 4 cols x 4 rows.
// Pre = prefetched first weight iteration (loaded before the barrier).
// ============================================================================
struct WPre { float4 e, o; };

template<int N, int K>
__device__ __forceinline__ WPre wpref(const float* __restrict__ Wp, int t)
{
    constexpr int CG = N / 4;
    constexpr int KS = NT / CG;
    constexpr int D2 = (K / KS) / 2;
    const int cg = t & (CG - 1);
    const int ks = t / CG;
    const int j0 = cg * 4;
    const float4* __restrict__ base =
        reinterpret_cast<const float4*>(Wp + (size_t)(ks * D2) * (2 * N) + j0);
    WPre p;
    p.e = __ldg(base);
    p.o = __ldg(base + N / 4);
    return p;
}

template<int N, int K>
__device__ __forceinline__ void split_partial(
    const ull* __restrict__ sinu, float* __restrict__ red,
    const float* __restrict__ Wp, int t, WPre pre)
{
    constexpr int CG = N / 4;
    constexpr int KS = NT / CG;
    constexpr int D2 = (K / KS) / 2;
    const int cg = t & (CG - 1);
    const int ks = t / CG;
    const int j0 = cg * 4;

    ull acc[4][4];
    #pragma unroll
    for (int c = 0; c < 4; c++)
        #pragma unroll
        for (int r = 0; r < 4; r++) acc[c][r] = 0;

    const float4* __restrict__ wE =
        reinterpret_cast<const float4*>(Wp + (size_t)(ks * D2) * (2 * N) + j0);
    const float4* __restrict__ wO = wE + N / 4;
    const ull* __restrict__ x = sinu + ks * D2;

    #pragma unroll
    for (int d = 0; d < D2; d++) {
        float4 we = (d == 0) ? pre.e : __ldg(wE + d * (N / 2));
        float4 wo = (d == 0) ? pre.o : __ldg(wO + d * (N / 2));
        ull w0 = pack2f(we.x, wo.x);
        ull w1 = pack2f(we.y, wo.y);
        ull w2 = pack2f(we.z, wo.z);
        ull w3 = pack2f(we.w, wo.w);
        #pragma unroll
        for (int r = 0; r < 4; r++) {
            ull xv = x[r * AROW + d];
            ffma2(acc[0][r], xv, w0);
            ffma2(acc[1][r], xv, w1);
            ffma2(acc[2][r], xv, w2);
            ffma2(acc[3][r], xv, w3);
        }
    }
    #pragma unroll
    for (int r = 0; r < 4; r++) {
        float4 o = make_float4(lanesum(acc[0][r]), lanesum(acc[1][r]),
                               lanesum(acc[2][r]), lanesum(acc[3][r]));
        *reinterpret_cast<float4*>(red + (r * KS + ks) * N + j0) = o;
    }
}

// ---- reduce partials -> gelu -> activation buffer (float2 rows) ----
template<int N>
__device__ __forceinline__ void reduce_act(
    const float* __restrict__ red, ull* __restrict__ soutu,
    const float* __restrict__ bias, int t)
{
    constexpr int KS = 2048 / N;
    constexpr int J2 = N / 2;
    const int j2 = t & (J2 - 1);
    const int r  = (N == 256) ? (t >> 7) : (t >> 6);
    const ull* __restrict__ rp = reinterpret_cast<const ull*>(red);
    ull s = 0;
    #pragma unroll
    for (int k = 0; k < KS; k++)
        s = fadd2(s, rp[(r * KS + k) * J2 + j2]);
    const float2 bb = __ldg(reinterpret_cast<const float2*>(bias) + j2);
    s = fadd2(s, pack2f(bb.x, bb.y));
    float2 f = asf2(s);
    soutu[r * AROW + j2] = pack2f(gelu(f.x), gelu(f.y));
}

// ---- pc partial for NEXT target variable (runs on idle upper threads) ----
// half in {0,1}: items [half*256 .. half*256+255], tu = t & 255
__device__ __forceinline__ void pc_part(
    int half, int i, int tgt, int vmax,
    const float* __restrict__ s_val, const ull* __restrict__ s_adj2,
    const float* __restrict__ var_emb, ull* __restrict__ s_pc, int tu)
{
    const int id = half * 256 + tu;
    const int r  = id >> 7;
    const int j2 = id & 127;
    const float2 e = __ldg(reinterpret_cast<const float2*>(var_emb + tgt * DM) + j2);
    ull acc = pack2f(e.x, e.y);
    const float* vp = s_val + r * DM + j2 * 2;
    const ull* arow = s_adj2 + tgt * NV;
    #pragma unroll 4
    for (int v = 0; v < vmax; v++) {
        if (v == i) continue;                         // current var fused later
        ull x = *reinterpret_cast<const ull*>(vp + v * (4 * DM));
        ffma2(acc, x, arow[v]);
    }
    s_pc[r * AROW + j2] = acc;
}

// ============================================================================
// Main kernel
// ============================================================================
__global__ void __launch_bounds__(NT, 1) scm_kernel(
    const float* __restrict__ edge_logits,
    const float* __restrict__ var_emb,
    const float* __restrict__ pab,
    const float* __restrict__ mb1,
    const float* __restrict__ mb2,
    const float* __restrict__ mb3,
    float* __restrict__ out)
{
    extern __shared__ __align__(16) ull smem[];
    float* s_red  = reinterpret_cast<float*>(smem);          // 4096 ull = 32KB
    ull*   s_a    = smem + 4096;                             // 520 ull
    ull*   s_b    = smem + 4616;                             // 520 ull
    ull*   s_pc   = smem + 5136;                             // 520 ull
    ull*   s_adj2 = smem + 5656;                             // 1024 ull
    float* s_val  = reinterpret_cast<float*>(smem + 6680);   // 32768 fl = 128KB

    const int t = threadIdx.x;
    const int row0 = blockIdx.x * RPB;

    // adjacency: sigmoid((logits * offdiag)/0.5); diagonal -> 0.5 (splat ull)
    for (int idx = t; idx < NV * NV; idx += NT) {
        int ii = idx / NV, v = idx % NV;
        float z = (v == ii) ? 0.0f : edge_logits[v * NV + ii] * 2.0f;
        s_adj2[idx] = pack2(1.0f / (1.0f + expf(-z)));
    }
    // step 0 input: s_a = emb[0] (no parents yet)
    {
        const int j2 = t & 127;
        const int r  = t >> 7;
        const float2 e = __ldg(reinterpret_cast<const float2*>(var_emb) + j2);
        s_a[r * AROW + j2] = pack2f(e.x, e.y);
    }
    // prefetch pa weights for step 0
    WPre pre_pa = wpref<DM, DM>(g_wpack + OFF_PA, t);
    __syncthreads();

    for (int s = 0; s < NL * NV; s++) {
        const int i = s & 31;
        const bool last = (s >= 2 * NV);
        const bool has_tgt = (s < NL * NV - 1);
        const int tgt = (i + 1) & 31;
        // stable-set size for pc_part: target in layer 0 -> only v < i valid
        const int vmax = (s + 1 < NV) ? i : NV;

        // ---- pa: parent_input partials (input s_a) ; prefetch w1
        split_partial<DM, DM>(s_a, s_red, g_wpack + OFF_PA, t, pre_pa);
        WPre pre_w1 = wpref<MM, DM>(g_wpack + OFF_W1 + i * (DM * MM), t);
        __syncthreads();

        reduce_act<DM>(s_red, s_b, pab, t);
        __syncthreads();

        // ---- w1: 256 -> 128 ; prefetch w2
        split_partial<MM, DM>(s_b, s_red, g_wpack + OFF_W1 + i * (DM * MM), t, pre_w1);
        WPre pre_w2 = wpref<MM, MM>(g_wpack + OFF_W2 + i * (MM * MM), t);
        __syncthreads();

        if (t < 256) reduce_act<MM>(s_red, s_a, mb1 + i * MM, t);
        else if (has_tgt) pc_part(0, i, tgt, vmax, s_val, s_adj2, var_emb, s_pc, t & 255);
        __syncthreads();

        // ---- w2: 128 -> 128 ; prefetch w3
        split_partial<MM, MM>(s_a, s_red, g_wpack + OFF_W2 + i * (MM * MM), t, pre_w2);
        WPre pre_w3 = wpref<DM, MM>(g_wpack + OFF_W3 + i * (MM * DM), t);
        __syncthreads();

        if (t < 256) reduce_act<MM>(s_red, s_b, mb2 + i * MM, t);
        else if (has_tgt) pc_part(1, i, tgt, vmax, s_val, s_adj2, var_emb, s_pc, t & 255);
        __syncthreads();

        // ---- w3: 128 -> 256 (partials) ; prefetch pa for next step
        split_partial<DM, MM>(s_b, s_red, g_wpack + OFF_W3 + i * (MM * DM), t, pre_w3);
        pre_pa = wpref<DM, DM>(g_wpack + OFF_PA, t);
        __syncthreads();

        // ---- final: sum partials + bias + noise -> s_val, out (last layer),
        //      and fuse pc: s_a = s_pc + adj[i->tgt] * val_new
        {
            const int j2 = t & 127;
            const int r  = t >> 7;
            const ull* rp = reinterpret_cast<const ull*>(s_red);
            ull sm = 0;
            #pragma unroll
            for (int k = 0; k < 8; k++)
                sm = fadd2(sm, rp[(r * 8 + k) * 128 + j2]);
            const float2 b2 = __ldg(reinterpret_cast<const float2*>(mb3 + i * DM) + j2);
            long long gidx = ((long long)(row0 + r) * NV + i) * DM + j2 * 2;
            const float2 n2 = __ldg(reinterpret_cast<const float2*>(g_noise + gidx));
            float2 f = asf2(sm);
            float2 v2 = make_float2(f.x + b2.x + n2.x, f.y + b2.y + n2.y);
            *reinterpret_cast<float2*>(s_val + (i * 4 + r) * DM + j2 * 2) = v2;
            if (last) *reinterpret_cast<float2*>(out + gidx) = v2;
            if (has_tgt) {
                ull pcv = s_pc[r * AROW + j2];
                ffma2(pcv, pack2f(v2.x, v2.y), s_adj2[tgt * NV + i]);
                s_a[r * AROW + j2] = pcv;
            }
        }
        __syncthreads();
    }
}

// ============================================================================
// Launch
// ============================================================================
#define SCM_SMEM ((6680 + 16384) * 8)   // 184512 bytes

extern "C" void kernel_launch(void* const* d_in, const int* in_sizes, int n_in,
                              void* d_out, int out_size)
{
    const float* nz   = (const float*)d_in[0];
    const float* elog = (const float*)d_in[1];
    const float* emb  = (const float*)d_in[2];
    const float* paW  = (const float*)d_in[3];
    const float* pab  = (const float*)d_in[4];
    const float* mW1  = (const float*)d_in[5];
    const float* mb1  = (const float*)d_in[6];
    const float* mW2  = (const float*)d_in[7];
    const float* mb2  = (const float*)d_in[8];
    const float* mW3  = (const float*)d_in[9];
    const float* mb3  = (const float*)d_in[10];
    const float* neW  = (const float*)d_in[11];
    const float* neb  = (const float*)d_in[12];
    float* out = (float*)d_out;

    static float* wp = nullptr;
    if (!wp) cudaGetSymbolAddress((void**)&wp, g_wpack);

    cudaFuncSetAttribute(scm_kernel, cudaFuncAttributeMaxDynamicSharedMemorySize, SCM_SMEM);

    pack_kernel<DM, DM><<<dim3(64, 1),  256>>>(wp + OFF_PA, paW);
    pack_kernel<DM, MM><<<dim3(32, NV), 256>>>(wp + OFF_W1, mW1);
    pack_kernel<MM, MM><<<dim3(16, NV), 256>>>(wp + OFF_W2, mW2);
    pack_kernel<MM, DM><<<dim3(32, NV), 256>>>(wp + OFF_W3, mW3);
    noise_kernel<<<dim3(BATCH / 32, NV), 256>>>(nz, neW, neb);
    scm_kernel<<<NBLK, NT, SCM_SMEM>>>(elog, emb, pab, mb1, mb2, mb3, out);
}